// round 1
// baseline (speedup 1.0000x reference)
#include <cuda_runtime.h>
#include <math.h>
#include <stdint.h>

// ---------------- problem constants ----------------
#define BATCH 64
#define CCH   256          // C
#define HH    20
#define WW    20
#define NTOK  400          // H*W
#define NHEAD 8
#define HD    32           // C / heads
#define TOKS  (BATCH*NTOK) // 25600

// ---------------- scratch layout (floats) ----------------
constexpr size_t O_XT   = 0;                         // (B,N,C) src token-major
constexpr size_t O_QG   = O_XT   + (size_t)TOKS*256; // (B,N,512)
constexpr size_t O_KV   = O_QG   + (size_t)TOKS*512; // (B,N,512)
constexpr size_t O_QP   = O_KV   + (size_t)TOKS*512;
constexpr size_t O_QN   = O_QP   + (size_t)TOKS*256;
constexpr size_t O_KP   = O_QN   + (size_t)TOKS*256;
constexpr size_t O_KN   = O_KP   + (size_t)TOKS*256;
constexpr size_t O_V    = O_KN   + (size_t)TOKS*256;
constexpr size_t O_VD   = O_V    + (size_t)TOKS*256;
constexpr size_t O_KM   = O_VD   + (size_t)TOKS*256; // (B*8, 64)
constexpr size_t O_KVS  = O_KM   + (size_t)512*64;   // (B*8, 64,16)
constexpr size_t O_KVO  = O_KVS  + (size_t)512*1024;
constexpr size_t O_OUT2 = O_KVO  + (size_t)512*1024; // (B,N,C)
constexpr size_t O_A    = O_OUT2 + (size_t)TOKS*256;
constexpr size_t O_S    = O_A    + (size_t)TOKS*256;
constexpr size_t O_Y    = O_S    + (size_t)TOKS*256; // (B,N,1024)
constexpr size_t O_Y2   = O_Y    + (size_t)TOKS*1024;// (B,N,512)
constexpr size_t O_F    = O_Y2   + (size_t)TOKS*512;
constexpr size_t O_TMP  = O_F    + (size_t)TOKS*256;
constexpr size_t O_SE   = O_TMP  + (size_t)TOKS*256; // (B,512)
constexpr size_t O_INV  = O_SE   + (size_t)BATCH*512;// 256
constexpr size_t O_PW   = O_INV  + 256;              // 256
constexpr size_t SCR_TOTAL = O_PW + 256;

__device__ float d_scratch[SCR_TOTAL];

// ---------------- small param prep ----------------
__global__ void k_prep(const float* __restrict__ scale, const float* __restrict__ power,
                       float* __restrict__ invsc, float* __restrict__ pw) {
    int c = threadIdx.x;
    float sp = log1pf(expf(scale[c]));          // softplus
    invsc[c] = 1.0f / sp;
    pw[c] = 1.0f + 4.0f / (1.0f + expf(-power[c]));
}

// ---------------- transpose (B,C,400) -> (B,400,C) ----------------
__global__ void k_tr_src(const float* __restrict__ src, float* __restrict__ XT) {
    __shared__ float tile[32][33];
    int b = blockIdx.z, cb = blockIdx.y * 32, nb = blockIdx.x * 32;
    int tx = threadIdx.x, ty = threadIdx.y;
    int n = nb + tx, c = cb + ty;
    if (n < NTOK) tile[ty][tx] = src[(size_t)b*CCH*NTOK + (size_t)c*NTOK + n];
    __syncthreads();
    n = nb + ty; c = cb + tx;
    if (n < NTOK) XT[((size_t)b*NTOK + n)*CCH + c] = tile[tx][ty];
}

// ---------------- transpose (B,400,C) -> (B,C,400) ----------------
__global__ void k_tr_out(const float* __restrict__ TMP, float* __restrict__ OUT) {
    __shared__ float tile[32][33];
    int b = blockIdx.z, cb = blockIdx.y * 32, nb = blockIdx.x * 32;
    int tx = threadIdx.x, ty = threadIdx.y;
    int n = nb + ty, c = cb + tx;
    if (n < NTOK) tile[ty][tx] = TMP[((size_t)b*NTOK + n)*CCH + c];
    __syncthreads();
    c = cb + ty; n = nb + tx;
    if (n < NTOK) OUT[(size_t)b*CCH*NTOK + (size_t)c*NTOK + n] = tile[tx][ty];
}

// ---------------- tiled SGEMM:  C[m,n] = sum_k A[m,k]*B[n,k] (+bias[n]) ----------------
// A: MxK row-major, B: NxK row-major. M%64==0, N%64==0, K%16==0.
__global__ __launch_bounds__(256)
void gemm_nt(const float* __restrict__ A, const float* __restrict__ B,
             const float* __restrict__ bias, float* __restrict__ C,
             int M, int N, int K) {
    __shared__ __align__(16) float As[16][68];
    __shared__ __align__(16) float Bs[16][68];
    int bm = blockIdx.y * 64, bn = blockIdx.x * 64;
    int t = threadIdx.x;
    int lrow = t >> 2;          // 0..63
    int lcol = (t & 3) << 2;    // 0,4,8,12
    int ty = t >> 4, tx = t & 15;
    float acc[4][4];
#pragma unroll
    for (int i = 0; i < 4; i++)
#pragma unroll
        for (int j = 0; j < 4; j++) acc[i][j] = 0.0f;

    const float* Ap = A + (size_t)(bm + lrow) * K + lcol;
    const float* Bp = B + (size_t)(bn + lrow) * K + lcol;

    for (int k0 = 0; k0 < K; k0 += 16) {
        float4 a4 = *(const float4*)(Ap + k0);
        float4 b4 = *(const float4*)(Bp + k0);
        As[lcol+0][lrow]=a4.x; As[lcol+1][lrow]=a4.y; As[lcol+2][lrow]=a4.z; As[lcol+3][lrow]=a4.w;
        Bs[lcol+0][lrow]=b4.x; Bs[lcol+1][lrow]=b4.y; Bs[lcol+2][lrow]=b4.z; Bs[lcol+3][lrow]=b4.w;
        __syncthreads();
#pragma unroll
        for (int kk = 0; kk < 16; kk++) {
            float4 av = *(const float4*)&As[kk][ty*4];
            float4 bv = *(const float4*)&Bs[kk][tx*4];
            float ar[4] = {av.x, av.y, av.z, av.w};
            float br[4] = {bv.x, bv.y, bv.z, bv.w};
#pragma unroll
            for (int i = 0; i < 4; i++)
#pragma unroll
                for (int j = 0; j < 4; j++) acc[i][j] += ar[i] * br[j];
        }
        __syncthreads();
    }
#pragma unroll
    for (int i = 0; i < 4; i++) {
        int m = bm + ty*4 + i;
        float4 o;
        int n0 = bn + tx*4;
        o.x = acc[i][0]; o.y = acc[i][1]; o.z = acc[i][2]; o.w = acc[i][3];
        if (bias) { o.x += bias[n0]; o.y += bias[n0+1]; o.z += bias[n0+2]; o.w += bias[n0+3]; }
        *(float4*)&C[(size_t)m * N + n0] = o;
    }
}

// ---------------- attention prep: pow activations, V extract ----------------
__global__ void k_attn_prep(const float* __restrict__ QG, const float* __restrict__ KV,
                            const float* __restrict__ pos,
                            const float* __restrict__ invsc, const float* __restrict__ pw,
                            float* __restrict__ QP, float* __restrict__ QN,
                            float* __restrict__ KP, float* __restrict__ KN,
                            float* __restrict__ V) {
    int tk = blockIdx.x;            // token 0..25599
    int c  = threadIdx.x;           // channel
    int n  = tk % NTOK;
    size_t b512 = (size_t)tk * 512;
    size_t b256 = (size_t)tk * 256;
    float is = invsc[c], p = pw[c];

    float q = QG[b512 + c] * is;
    float qp = 0.f, qn = 0.f;
    if (q > 0.f)      qp = powf(fmaxf(q, 1e-30f), p);
    else if (q < 0.f) qn = powf(fmaxf(-q, 1e-30f), p);
    QP[b256 + c] = qp; QN[b256 + c] = qn;

    float k = (KV[b512 + c] + pos[(size_t)n*256 + c]) * is;
    float kp = 0.f, kn = 0.f;
    if (k > 0.f)      kp = powf(fmaxf(k, 1e-30f), p);
    else if (k < 0.f) kn = powf(fmaxf(-k, 1e-30f), p);
    KP[b256 + c] = kp; KN[b256 + c] = kn;

    V[b256 + c] = KV[b512 + 256 + c];
}

// ---------------- per-(b,h): k_mean(64), kv_sim(64x16), kv_opp(64x16) ----------------
__global__ __launch_bounds__(256)
void k_reduce(const float* __restrict__ KP, const float* __restrict__ KN,
              const float* __restrict__ V,
              float* __restrict__ KM, float* __restrict__ KVS, float* __restrict__ KVO) {
    int bh = blockIdx.x, b = bh >> 3, h = bh & 7;
    __shared__ float kc_s[16][64];
    __shared__ float v_s[16][32];
    int t = threadIdx.x;
    int j = t >> 2, e0 = (t & 3) << 2;
    float accs[4] = {0,0,0,0}, acco[4] = {0,0,0,0}, accm = 0.f;

    for (int n0 = 0; n0 < NTOK; n0 += 16) {
        for (int idx = t; idx < 16*64; idx += 256) {
            int nl = idx >> 6, jj = idx & 63;
            size_t base = ((size_t)(b*NTOK + n0 + nl))*256 + h*32 + (jj & 31);
            kc_s[nl][jj] = (jj < 32) ? KP[base] : KN[base];
        }
        for (int idx = t; idx < 16*32; idx += 256) {
            int nl = idx >> 5, ee = idx & 31;
            size_t base = ((size_t)(b*NTOK + n0 + nl))*256 + (ee < 16 ? h*16 + ee : 128 + h*16 + ee - 16);
            v_s[nl][ee] = V[base];
        }
        __syncthreads();
#pragma unroll
        for (int nl = 0; nl < 16; nl++) {
            float kcv = kc_s[nl][j];
            accm += kcv;
#pragma unroll
            for (int q = 0; q < 4; q++) {
                accs[q] += kcv * v_s[nl][e0 + q];
                acco[q] += kcv * v_s[nl][16 + e0 + q];
            }
        }
        __syncthreads();
    }
    const float invN = 1.0f / (float)NTOK;
    size_t ob = (size_t)bh*1024 + (size_t)j*16 + e0;
#pragma unroll
    for (int q = 0; q < 4; q++) { KVS[ob+q] = accs[q]*invN; KVO[ob+q] = acco[q]*invN; }
    if ((t & 3) == 0) KM[(size_t)bh*64 + j] = accm * invN;
}

// ---------------- depthwise 5x5 on reinterpreted v ----------------
// V flat per batch: idx = g*12800 + y*640 + x*32 + d  (== n*256 + c)
__global__ __launch_bounds__(256)
void k_dwc(const float* __restrict__ V, const float* __restrict__ w,
           const float* __restrict__ bias, float* __restrict__ VD) {
    __shared__ float tile[14*640];
    __shared__ float ws[800];
    __shared__ float bs[32];
    int blk = blockIdx.x;             // b*16 + g*2 + half
    int half = blk & 1, g = (blk >> 1) & 7, b = blk >> 4;
    int t = threadIdx.x;
    for (int i = t; i < 800; i += 256) ws[i] = w[i];
    if (t < 32) bs[t] = bias[t];
    const float* Vb = V + (size_t)b*102400 + (size_t)g*12800;
    int r0 = half*10 - 2;
    for (int i = t; i < 14*640; i += 256) {
        int rr = i / 640, rem = i - rr*640;
        int r = r0 + rr;
        tile[i] = (r >= 0 && r < 20) ? Vb[r*640 + rem] : 0.0f;
    }
    __syncthreads();
    for (int oi = t; oi < 10*640; oi += 256) {
        int yl = oi / 640, rem = oi - yl*640;
        int x = rem >> 5, dd = rem & 31;
        int lrow = yl + 2;
        float acc = bs[dd];
#pragma unroll
        for (int ky = 0; ky < 5; ky++) {
#pragma unroll
            for (int kx = 0; kx < 5; kx++) {
                int xx = x + kx - 2;
                if (xx >= 0 && xx < 20)
                    acc += tile[(lrow + ky - 2)*640 + xx*32 + dd] * ws[dd*25 + ky*5 + kx];
            }
        }
        int y = half*10 + yl;
        VD[(size_t)b*102400 + (size_t)g*12800 + (size_t)y*640 + rem] = acc;
    }
}

// ---------------- attention output + vd + gate ----------------
__global__ __launch_bounds__(256)
void k_attn_out(const float* __restrict__ QP, const float* __restrict__ QN,
                const float* __restrict__ KM, const float* __restrict__ KVS,
                const float* __restrict__ KVO, const float* __restrict__ VD,
                const float* __restrict__ QG, float* __restrict__ OUT2) {
    int bh = blockIdx.x, b = bh >> 3, h = bh & 7;
    __shared__ float km_s[64];
    __shared__ float kvb[64][32];     // [:, :16]=kv_sim, [:,16:]=kv_opp
    __shared__ float qps[8][32], qns[8][32];
    int t = threadIdx.x, w = t >> 5, d = t & 31;
    for (int idx = t; idx < 64; idx += 256) km_s[idx] = KM[(size_t)bh*64 + idx];
    for (int idx = t; idx < 2048; idx += 256) {
        int j = idx >> 5, col = idx & 31;
        kvb[j][col] = (col < 16) ? KVS[(size_t)bh*1024 + j*16 + col]
                                 : KVO[(size_t)bh*1024 + j*16 + (col - 16)];
    }
    __syncthreads();
    bool sim = (d < 16);
    for (int n0 = 0; n0 < NTOK; n0 += 8) {
        int n = n0 + w;
        size_t tokbase = ((size_t)(b*NTOK + n)) * 256;
        float qp = QP[tokbase + h*32 + d];
        float qn = QN[tokbase + h*32 + d];
        qps[w][d] = qp; qns[w][d] = qn;
        __syncwarp();
        float d1 = qp*km_s[d] + qn*km_s[32 + d];
        float d2 = qn*km_s[d] + qp*km_s[32 + d];
#pragma unroll
        for (int off = 16; off; off >>= 1) {
            d1 += __shfl_xor_sync(0xffffffffu, d1, off);
            d2 += __shfl_xor_sync(0xffffffffu, d2, off);
        }
        float acc = 0.f;
#pragma unroll
        for (int j = 0; j < 32; j++) {
            float a = qps[w][j], bb = qns[w][j];
            float m1 = sim ? a : bb;
            float m2 = sim ? bb : a;
            acc += m1*kvb[j][d] + m2*kvb[32 + j][d];
        }
        float den = (sim ? d1 : d2) + 1e-6f;
        float val = acc / den;
        int c = h*32 + d;
        float vdv = VD[(size_t)b*102400 + (size_t)n*256 + c];
        float gg  = QG[((size_t)(b*NTOK + n))*512 + 256 + c];
        OUT2[tokbase + c] = (val + vdv) * gg;
        __syncwarp();
    }
}

// ---------------- block reduce helper ----------------
__device__ __forceinline__ float blk_sum256(float v, volatile float* sw) {
    int t = threadIdx.x;
#pragma unroll
    for (int off = 16; off; off >>= 1) v += __shfl_xor_sync(0xffffffffu, v, off);
    __syncthreads();
    if ((t & 31) == 0) sw[t >> 5] = v;
    __syncthreads();
    return sw[0]+sw[1]+sw[2]+sw[3]+sw[4]+sw[5]+sw[6]+sw[7];
}

// ---------------- channel layernorm over C per token, out token-major ----------------
__global__ void k_ln(const float* __restrict__ X1, const float* __restrict__ X2,
                     const float* __restrict__ w, const float* __restrict__ bb,
                     float* __restrict__ OUT) {
    __shared__ float shm[8];
    int tk = blockIdx.x, c = threadIdx.x;
    size_t base = (size_t)tk * 256;
    float v = X1[base + c] + X2[base + c];
    float mean = blk_sum256(v, shm) * (1.0f/256.0f);
    float dv = v - mean;
    float var = blk_sum256(dv*dv, shm) * (1.0f/256.0f);
    OUT[base + c] = w[c] * dv * rsqrtf(var + 1e-6f) + bb[c];
}

// ---------------- SE: sigmoid(se_w @ mean_spatial(src)) ----------------
__global__ void k_se(const float* __restrict__ src, const float* __restrict__ sew,
                     float* __restrict__ SE) {
    int b = blockIdx.x, t = threadIdx.x, w = t >> 5, lane = t & 31;
    __shared__ float sm[256];
    for (int ci = 0; ci < 32; ci++) {
        int c = w*32 + ci;
        const float* p = src + (size_t)b*102400 + (size_t)c*400;
        float s = 0.f;
        for (int n = lane; n < 400; n += 32) s += p[n];
#pragma unroll
        for (int off = 16; off; off >>= 1) s += __shfl_xor_sync(0xffffffffu, s, off);
        if (lane == 0) sm[c] = s * (1.0f/400.0f);
    }
    __syncthreads();
    for (int o = t; o < 512; o += 256) {
        const float* wr = sew + (size_t)o*256;
        float acc = 0.f;
        for (int c = 0; c < 256; c++) acc += wr[c] * sm[c];
        SE[(size_t)b*512 + o] = 1.0f / (1.0f + expf(-acc));
    }
}

// ---------------- depthwise 3x3 + GLU(gelu) + SE scale ----------------
__global__ __launch_bounds__(256)
void k_dw_glu(const float* __restrict__ Y, const float* __restrict__ dww,
              const float* __restrict__ SE, float* __restrict__ Y2) {
    int y = blockIdx.x, b = blockIdx.y;
    int t = threadIdx.x;
    for (int idx = t; idx < 20*512; idx += 256) {
        int x = idx >> 9, ch = idx & 511;
        float s1 = 0.f, s2 = 0.f;
#pragma unroll
        for (int ky = 0; ky < 3; ky++) {
            int yy = y + ky - 1;
            if (yy < 0 || yy >= 20) continue;
#pragma unroll
            for (int kx = 0; kx < 3; kx++) {
                int xx = x + kx - 1;
                if (xx < 0 || xx >= 20) continue;
                size_t ib = ((size_t)(b*NTOK + yy*20 + xx)) * 1024;
                s1 += Y[ib + ch]       * dww[ch*9 + ky*3 + kx];
                s2 += Y[ib + 512 + ch] * dww[(ch + 512)*9 + ky*3 + kx];
            }
        }
        float ge = 0.5f * s1 * (1.0f + erff(s1 * 0.70710678118654752f));
        Y2[((size_t)(b*NTOK + y*20 + x))*512 + ch] = ge * s2 * SE[(size_t)b*512 + ch];
    }
}

// ---------------- launcher ----------------
extern "C" void kernel_launch(void* const* d_in, const int* in_sizes, int n_in,
                              void* d_out, int out_size) {
    const float* src    = (const float*)d_in[0];
    const float* qg_w   = (const float*)d_in[1];
    const float* qg_b   = (const float*)d_in[2];
    const float* kv_w   = (const float*)d_in[3];
    const float* kv_b   = (const float*)d_in[4];
    const float* proj_w = (const float*)d_in[5];
    const float* proj_b = (const float*)d_in[6];
    const float* dwc_w  = (const float*)d_in[7];
    const float* dwc_b  = (const float*)d_in[8];
    const float* power  = (const float*)d_in[9];
    const float* scale  = (const float*)d_in[10];
    const float* pos    = (const float*)d_in[11];
    const float* pin_w  = (const float*)d_in[12];
    const float* dw_w   = (const float*)d_in[13];
    const float* se_w   = (const float*)d_in[14];
    const float* pout_w = (const float*)d_in[15];
    const float* ln1_w  = (const float*)d_in[16];
    const float* ln1_b  = (const float*)d_in[17];
    const float* ln2_w  = (const float*)d_in[18];
    const float* ln2_b  = (const float*)d_in[19];
    float* out = (float*)d_out;

    float* scr = nullptr;
    cudaGetSymbolAddress((void**)&scr, d_scratch);

    float* XT   = scr + O_XT;
    float* QG   = scr + O_QG;
    float* KV   = scr + O_KV;
    float* QP   = scr + O_QP;
    float* QN   = scr + O_QN;
    float* KP   = scr + O_KP;
    float* KN   = scr + O_KN;
    float* V    = scr + O_V;
    float* VD   = scr + O_VD;
    float* KM   = scr + O_KM;
    float* KVS  = scr + O_KVS;
    float* KVO  = scr + O_KVO;
    float* OUT2 = scr + O_OUT2;
    float* A    = scr + O_A;
    float* S    = scr + O_S;
    float* Y    = scr + O_Y;
    float* Y2   = scr + O_Y2;
    float* F    = scr + O_F;
    float* TMP  = scr + O_TMP;
    float* SE   = scr + O_SE;
    float* INV  = scr + O_INV;
    float* PW   = scr + O_PW;

    // 1. params
    k_prep<<<1, 256>>>(scale, power, INV, PW);
    // 2. src -> token-major
    k_tr_src<<<dim3(13, 8, BATCH), dim3(32, 32)>>>(src, XT);
    // 3. qg / kv GEMMs
    gemm_nt<<<dim3(8, 400), 256>>>(XT, qg_w, qg_b, QG, TOKS, 512, 256);
    gemm_nt<<<dim3(8, 400), 256>>>(XT, kv_w, kv_b, KV, TOKS, 512, 256);
    // 4. pow activations + V extract
    k_attn_prep<<<TOKS, 256>>>(QG, KV, pos, INV, PW, QP, QN, KP, KN, V);
    // 5. per-(b,h) reductions
    k_reduce<<<512, 256>>>(KP, KN, V, KM, KVS, KVO);
    // 6. depthwise 5x5 on reinterpreted v
    k_dwc<<<1024, 256>>>(V, dwc_w, dwc_b, VD);
    // 7. attention output + vd + gate
    k_attn_out<<<512, 256>>>(QP, QN, KM, KVS, KVO, VD, QG, OUT2);
    // 8. projection
    gemm_nt<<<dim3(4, 400), 256>>>(OUT2, proj_w, proj_b, A, TOKS, 256, 256);
    // 9. LN1: s = LN(src + a)
    k_ln<<<TOKS, 256>>>(XT, A, ln1_w, ln1_b, S);
    // 10. SE gate from raw src
    k_se<<<BATCH, 256>>>(src, se_w, SE);
    // 11. pin 1x1
    gemm_nt<<<dim3(16, 400), 256>>>(S, pin_w, nullptr, Y, TOKS, 1024, 256);
    // 12. dw 3x3 + glu + se
    k_dw_glu<<<dim3(20, BATCH), 256>>>(Y, dw_w, SE, Y2);
    // 13. pout 1x1
    gemm_nt<<<dim3(4, 400), 256>>>(Y2, pout_w, nullptr, F, TOKS, 256, 512);
    // 14. LN2
    k_ln<<<TOKS, 256>>>(S, F, ln2_w, ln2_b, TMP);
    // 15. transpose to NCHW output
    k_tr_out<<<dim3(13, 8, BATCH), dim3(32, 32)>>>(TMP, out);
}

// round 3
// speedup vs baseline: 1.5791x; 1.5791x over previous
#include <cuda_runtime.h>
#include <math.h>
#include <stdint.h>

// ---------------- problem constants ----------------
#define BATCH 64
#define CCH   256          // C
#define HH    20
#define WW    20
#define NTOK  400          // H*W
#define NHEAD 8
#define HD    32           // C / heads
#define TOKS  (BATCH*NTOK) // 25600

// ---------------- scratch layout (floats) ----------------
constexpr size_t O_XT   = 0;                         // (B,N,C) src token-major
constexpr size_t O_QG   = O_XT   + (size_t)TOKS*256; // (B,N,512)
constexpr size_t O_KV   = O_QG   + (size_t)TOKS*512; // (B,N,512)
constexpr size_t O_QP   = O_KV   + (size_t)TOKS*512;
constexpr size_t O_QN   = O_QP   + (size_t)TOKS*256;
constexpr size_t O_KP   = O_QN   + (size_t)TOKS*256;
constexpr size_t O_KN   = O_KP   + (size_t)TOKS*256;
constexpr size_t O_V    = O_KN   + (size_t)TOKS*256;
constexpr size_t O_VD   = O_V    + (size_t)TOKS*256;
constexpr size_t O_KM   = O_VD   + (size_t)TOKS*256; // (B*8, 64)
constexpr size_t O_KVS  = O_KM   + (size_t)512*64;   // (B*8, 64,16)
constexpr size_t O_KVO  = O_KVS  + (size_t)512*1024;
constexpr size_t O_OUT2 = O_KVO  + (size_t)512*1024; // (B,N,C)
constexpr size_t O_A    = O_OUT2 + (size_t)TOKS*256;
constexpr size_t O_S    = O_A    + (size_t)TOKS*256;
constexpr size_t O_Y    = O_S    + (size_t)TOKS*256; // (B,N,1024)
constexpr size_t O_Y2   = O_Y    + (size_t)TOKS*1024;// (B,N,512)
constexpr size_t O_F    = O_Y2   + (size_t)TOKS*512;
constexpr size_t O_TMP  = O_F    + (size_t)TOKS*256;
constexpr size_t O_SE   = O_TMP  + (size_t)TOKS*256; // (B,512)
constexpr size_t O_INV  = O_SE   + (size_t)BATCH*512;// 256
constexpr size_t O_PW   = O_INV  + 256;              // 256
constexpr size_t SCR_TOTAL = O_PW + 256;

__device__ __align__(256) float d_scratch[SCR_TOTAL];

// =======================================================================
// mma.sync TF32 GEMM (sm_80+ PTX path — compiles for compute_100)
// C[m,n] = sum_k A[m,k]*B[n,k] (+bias[n])
// CTA tile 128x128, K-chunk 32, 8 warps, warp tile 64x32.
// SPLIT==3: 3xTF32 error compensation; SPLIT==1: plain tf32.
// M%128==0, N%128==0, K%32==0.
// =======================================================================

__device__ __forceinline__ uint32_t smem_u32(const void* p) {
    uint32_t a;
    asm("{ .reg .u64 t; cvta.to.shared.u64 t, %1; cvt.u32.u64 %0, t; }" : "=r"(a) : "l"(p));
    return a;
}
__device__ __forceinline__ uint32_t f2tf32(float x) {
    uint32_t u; asm("cvt.rna.tf32.f32 %0, %1;" : "=r"(u) : "f"(x)); return u;
}
__device__ __forceinline__ void cp16(uint32_t s, const void* g) {
    asm volatile("cp.async.ca.shared.global [%0], [%1], 16;" :: "r"(s), "l"(g));
}
#define CP_COMMIT() asm volatile("cp.async.commit_group;" ::: "memory")
#define CP_WAIT(n)  asm volatile("cp.async.wait_group %0;" :: "n"(n) : "memory")

__device__ __forceinline__ void mma_tf32(float* d, const uint32_t* a, const uint32_t* b) {
    asm volatile(
        "mma.sync.aligned.m16n8k8.row.col.f32.tf32.tf32.f32 "
        "{%0,%1,%2,%3}, {%4,%5,%6,%7}, {%8,%9}, {%0,%1,%2,%3};"
        : "+f"(d[0]), "+f"(d[1]), "+f"(d[2]), "+f"(d[3])
        : "r"(a[0]), "r"(a[1]), "r"(a[2]), "r"(a[3]), "r"(b[0]), "r"(b[1]));
}

// smem: per buffer: A[128][36] + B[128][36] floats = 9216 floats; double buffered.
constexpr int GS_ROW   = 36;                  // padded row stride (floats)
constexpr int GS_TILE  = 128 * GS_ROW;        // 4608 floats
constexpr int GS_BUF   = 2 * GS_TILE;         // 9216 floats (A + B)
constexpr int SMEM_GEMM = 2 * GS_BUF * 4;     // 73728 bytes

template<int SPLIT>
__global__ __launch_bounds__(256)
void gemm_mma(const float* __restrict__ A, const float* __restrict__ Bw,
              const float* __restrict__ bias, float* __restrict__ C,
              int M, int N, int K) {
    extern __shared__ float sm[];
    const uint32_t sbase = smem_u32(sm);
    const int t = threadIdx.x, lane = t & 31, wid = t >> 5;
    const int wm = (wid >> 2) * 64;           // 0 or 64
    const int wn = (wid & 3) * 32;            // 0..96
    const int bm = blockIdx.y * 128, bn = blockIdx.x * 128;
    const int g4 = lane >> 2, l4 = lane & 3;
    const int NC = K >> 5;

    // cp.async loader: 2048 x 16B per chunk (A rows then B rows), 8 per thread
    auto load_chunk = [&](int ch, int buf) {
        int k0 = ch << 5;
        uint32_t sb = sbase + (uint32_t)buf * (GS_BUF * 4);
#pragma unroll
        for (int i = 0; i < 8; i++) {
            int o = t + i * 256;              // 0..2047
            int isB = o >> 10;
            int row = (o & 1023) >> 3;
            int seg = o & 7;
            const float* g = (isB ? Bw + (size_t)(bn + row) * K
                                  : A  + (size_t)(bm + row) * K) + k0 + seg * 4;
            uint32_t s = sb + (uint32_t)(isB * (GS_TILE * 4) + row * (GS_ROW * 4) + seg * 16);
            cp16(s, g);
        }
        CP_COMMIT();
    };

    float acc[4][4][4];
#pragma unroll
    for (int mi = 0; mi < 4; mi++)
#pragma unroll
        for (int ni = 0; ni < 4; ni++)
#pragma unroll
            for (int k = 0; k < 4; k++) acc[mi][ni][k] = 0.0f;

    load_chunk(0, 0);
    if (NC > 1) load_chunk(1, 1);

    for (int ch = 0; ch < NC; ch++) {
        if (ch + 1 < NC) { CP_WAIT(1); } else { CP_WAIT(0); }
        __syncthreads();
        const float* Ab = sm + (ch & 1) * GS_BUF;
        const float* Bb = Ab + GS_TILE;
#pragma unroll
        for (int s = 0; s < 4; s++) {
            int c0 = s * 8 + l4;
            uint32_t ah[4][4], al[4][4];
            uint32_t bh[4][2], bl[4][2];
#pragma unroll
            for (int mi = 0; mi < 4; mi++) {
                const float* ap = Ab + (wm + mi * 16 + g4) * GS_ROW;
                float x0 = ap[c0], x1 = ap[8 * GS_ROW + c0];
                float x2 = ap[c0 + 4], x3 = ap[8 * GS_ROW + c0 + 4];
                ah[mi][0] = f2tf32(x0); ah[mi][1] = f2tf32(x1);
                ah[mi][2] = f2tf32(x2); ah[mi][3] = f2tf32(x3);
                if (SPLIT == 3) {
                    al[mi][0] = f2tf32(x0 - __uint_as_float(ah[mi][0]));
                    al[mi][1] = f2tf32(x1 - __uint_as_float(ah[mi][1]));
                    al[mi][2] = f2tf32(x2 - __uint_as_float(ah[mi][2]));
                    al[mi][3] = f2tf32(x3 - __uint_as_float(ah[mi][3]));
                }
            }
#pragma unroll
            for (int ni = 0; ni < 4; ni++) {
                const float* bp = Bb + (wn + ni * 8 + g4) * GS_ROW;
                float y0 = bp[c0], y1 = bp[c0 + 4];
                bh[ni][0] = f2tf32(y0); bh[ni][1] = f2tf32(y1);
                if (SPLIT == 3) {
                    bl[ni][0] = f2tf32(y0 - __uint_as_float(bh[ni][0]));
                    bl[ni][1] = f2tf32(y1 - __uint_as_float(bh[ni][1]));
                }
            }
#pragma unroll
            for (int mi = 0; mi < 4; mi++)
#pragma unroll
                for (int ni = 0; ni < 4; ni++) {
                    mma_tf32(acc[mi][ni], ah[mi], bh[ni]);
                    if (SPLIT == 3) {
                        mma_tf32(acc[mi][ni], ah[mi], bl[ni]);
                        mma_tf32(acc[mi][ni], al[mi], bh[ni]);
                    }
                }
        }
        __syncthreads();
        if (ch + 2 < NC) load_chunk(ch + 2, ch & 1);
    }

    // epilogue
#pragma unroll
    for (int mi = 0; mi < 4; mi++) {
        int r0 = bm + wm + mi * 16 + g4;
#pragma unroll
        for (int ni = 0; ni < 4; ni++) {
            int cb = bn + wn + ni * 8 + 2 * l4;
            float b0 = 0.f, b1 = 0.f;
            if (bias) { b0 = bias[cb]; b1 = bias[cb + 1]; }
            float2 v0 = make_float2(acc[mi][ni][0] + b0, acc[mi][ni][1] + b1);
            float2 v1 = make_float2(acc[mi][ni][2] + b0, acc[mi][ni][3] + b1);
            *(float2*)&C[(size_t)r0 * N + cb]       = v0;
            *(float2*)&C[(size_t)(r0 + 8) * N + cb] = v1;
        }
    }
}

// ---------------- small param prep ----------------
__global__ void k_prep(const float* __restrict__ scale, const float* __restrict__ power,
                       float* __restrict__ invsc, float* __restrict__ pw) {
    int c = threadIdx.x;
    float sp = log1pf(expf(scale[c]));          // softplus
    invsc[c] = 1.0f / sp;
    pw[c] = 1.0f + 4.0f / (1.0f + expf(-power[c]));
}

// ---------------- transpose (B,C,400) -> (B,400,C) ----------------
__global__ void k_tr_src(const float* __restrict__ src, float* __restrict__ XT) {
    __shared__ float tile[32][33];
    int b = blockIdx.z, cb = blockIdx.y * 32, nb = blockIdx.x * 32;
    int tx = threadIdx.x, ty = threadIdx.y;
    int n = nb + tx, c = cb + ty;
    if (n < NTOK) tile[ty][tx] = src[(size_t)b*CCH*NTOK + (size_t)c*NTOK + n];
    __syncthreads();
    n = nb + ty; c = cb + tx;
    if (n < NTOK) XT[((size_t)b*NTOK + n)*CCH + c] = tile[tx][ty];
}

// ---------------- transpose (B,400,C) -> (B,C,400) ----------------
__global__ void k_tr_out(const float* __restrict__ TMP, float* __restrict__ OUT) {
    __shared__ float tile[32][33];
    int b = blockIdx.z, cb = blockIdx.y * 32, nb = blockIdx.x * 32;
    int tx = threadIdx.x, ty = threadIdx.y;
    int n = nb + ty, c = cb + tx;
    if (n < NTOK) tile[ty][tx] = TMP[((size_t)b*NTOK + n)*CCH + c];
    __syncthreads();
    c = cb + ty; n = nb + tx;
    if (n < NTOK) OUT[(size_t)b*CCH*NTOK + (size_t)c*NTOK + n] = tile[tx][ty];
}

// ---------------- attention prep: pow activations, V extract ----------------
__global__ void k_attn_prep(const float* __restrict__ QG, const float* __restrict__ KV,
                            const float* __restrict__ pos,
                            const float* __restrict__ invsc, const float* __restrict__ pw,
                            float* __restrict__ QP, float* __restrict__ QN,
                            float* __restrict__ KP, float* __restrict__ KN,
                            float* __restrict__ V) {
    int tk = blockIdx.x;            // token 0..25599
    int c  = threadIdx.x;           // channel
    int n  = tk % NTOK;
    size_t b512 = (size_t)tk * 512;
    size_t b256 = (size_t)tk * 256;
    float is = invsc[c], p = pw[c];

    float q = QG[b512 + c] * is;
    float qp = 0.f, qn = 0.f;
    if (q > 0.f)      qp = __powf(fmaxf(q, 1e-30f), p);
    else if (q < 0.f) qn = __powf(fmaxf(-q, 1e-30f), p);
    QP[b256 + c] = qp; QN[b256 + c] = qn;

    float k = (KV[b512 + c] + pos[(size_t)n*256 + c]) * is;
    float kp = 0.f, kn = 0.f;
    if (k > 0.f)      kp = __powf(fmaxf(k, 1e-30f), p);
    else if (k < 0.f) kn = __powf(fmaxf(-k, 1e-30f), p);
    KP[b256 + c] = kp; KN[b256 + c] = kn;

    V[b256 + c] = KV[b512 + 256 + c];
}

// ---------------- per-(b,h): k_mean(64), kv_sim(64x16), kv_opp(64x16) ----------------
__global__ __launch_bounds__(256)
void k_reduce(const float* __restrict__ KP, const float* __restrict__ KN,
              const float* __restrict__ V,
              float* __restrict__ KM, float* __restrict__ KVS, float* __restrict__ KVO) {
    int bh = blockIdx.x, b = bh >> 3, h = bh & 7;
    __shared__ float kc_s[16][64];
    __shared__ float v_s[16][32];
    int t = threadIdx.x;
    int j = t >> 2, e0 = (t & 3) << 2;
    float accs[4] = {0,0,0,0}, acco[4] = {0,0,0,0}, accm = 0.f;

    for (int n0 = 0; n0 < NTOK; n0 += 16) {
        for (int idx = t; idx < 16*64; idx += 256) {
            int nl = idx >> 6, jj = idx & 63;
            size_t base = ((size_t)(b*NTOK + n0 + nl))*256 + h*32 + (jj & 31);
            kc_s[nl][jj] = (jj < 32) ? KP[base] : KN[base];
        }
        for (int idx = t; idx < 16*32; idx += 256) {
            int nl = idx >> 5, ee = idx & 31;
            size_t base = ((size_t)(b*NTOK + n0 + nl))*256 + (ee < 16 ? h*16 + ee : 128 + h*16 + ee - 16);
            v_s[nl][ee] = V[base];
        }
        __syncthreads();
#pragma unroll
        for (int nl = 0; nl < 16; nl++) {
            float kcv = kc_s[nl][j];
            accm += kcv;
#pragma unroll
            for (int q = 0; q < 4; q++) {
                accs[q] += kcv * v_s[nl][e0 + q];
                acco[q] += kcv * v_s[nl][16 + e0 + q];
            }
        }
        __syncthreads();
    }
    const float invN = 1.0f / (float)NTOK;
    size_t ob = (size_t)bh*1024 + (size_t)j*16 + e0;
#pragma unroll
    for (int q = 0; q < 4; q++) { KVS[ob+q] = accs[q]*invN; KVO[ob+q] = acco[q]*invN; }
    if ((t & 3) == 0) KM[(size_t)bh*64 + j] = accm * invN;
}

// ---------------- depthwise 5x5 on reinterpreted v ----------------
__global__ __launch_bounds__(256)
void k_dwc(const float* __restrict__ V, const float* __restrict__ w,
           const float* __restrict__ bias, float* __restrict__ VD) {
    __shared__ float tile[14*640];
    __shared__ float ws[800];
    __shared__ float bs[32];
    int blk = blockIdx.x;             // b*16 + g*2 + half
    int half = blk & 1, g = (blk >> 1) & 7, b = blk >> 4;
    int t = threadIdx.x;
    for (int i = t; i < 800; i += 256) ws[i] = w[i];
    if (t < 32) bs[t] = bias[t];
    const float* Vb = V + (size_t)b*102400 + (size_t)g*12800;
    int r0 = half*10 - 2;
    for (int i = t; i < 14*640; i += 256) {
        int rr = i / 640, rem = i - rr*640;
        int r = r0 + rr;
        tile[i] = (r >= 0 && r < 20) ? Vb[r*640 + rem] : 0.0f;
    }
    __syncthreads();
    for (int oi = t; oi < 10*640; oi += 256) {
        int yl = oi / 640, rem = oi - yl*640;
        int x = rem >> 5, dd = rem & 31;
        int lrow = yl + 2;
        float acc = bs[dd];
#pragma unroll
        for (int ky = 0; ky < 5; ky++) {
#pragma unroll
            for (int kx = 0; kx < 5; kx++) {
                int xx = x + kx - 2;
                if (xx >= 0 && xx < 20)
                    acc += tile[(lrow + ky - 2)*640 + xx*32 + dd] * ws[dd*25 + ky*5 + kx];
            }
        }
        int y = half*10 + yl;
        VD[(size_t)b*102400 + (size_t)g*12800 + (size_t)y*640 + rem] = acc;
    }
}

// ---------------- attention output + vd + gate ----------------
__global__ __launch_bounds__(256)
void k_attn_out(const float* __restrict__ QP, const float* __restrict__ QN,
                const float* __restrict__ KM, const float* __restrict__ KVS,
                const float* __restrict__ KVO, const float* __restrict__ VD,
                const float* __restrict__ QG, float* __restrict__ OUT2) {
    int bh = blockIdx.x, b = bh >> 3, h = bh & 7;
    __shared__ float km_s[64];
    __shared__ float kvb[64][32];     // [:, :16]=kv_sim, [:,16:]=kv_opp
    __shared__ float qps[8][32], qns[8][32];
    int t = threadIdx.x, w = t >> 5, d = t & 31;
    for (int idx = t; idx < 64; idx += 256) km_s[idx] = KM[(size_t)bh*64 + idx];
    for (int idx = t; idx < 2048; idx += 256) {
        int j = idx >> 5, col = idx & 31;
        kvb[j][col] = (col < 16) ? KVS[(size_t)bh*1024 + j*16 + col]
                                 : KVO[(size_t)bh*1024 + j*16 + (col - 16)];
    }
    __syncthreads();
    bool sim = (d < 16);
    for (int n0 = 0; n0 < NTOK; n0 += 8) {
        int n = n0 + w;
        size_t tokbase = ((size_t)(b*NTOK + n)) * 256;
        float qp = QP[tokbase + h*32 + d];
        float qn = QN[tokbase + h*32 + d];
        qps[w][d] = qp; qns[w][d] = qn;
        __syncwarp();
        float d1 = qp*km_s[d] + qn*km_s[32 + d];
        float d2 = qn*km_s[d] + qp*km_s[32 + d];
#pragma unroll
        for (int off = 16; off; off >>= 1) {
            d1 += __shfl_xor_sync(0xffffffffu, d1, off);
            d2 += __shfl_xor_sync(0xffffffffu, d2, off);
        }
        float acc = 0.f;
#pragma unroll
        for (int j = 0; j < 32; j++) {
            float a = qps[w][j], bb = qns[w][j];
            float m1 = sim ? a : bb;
            float m2 = sim ? bb : a;
            acc += m1*kvb[j][d] + m2*kvb[32 + j][d];
        }
        float den = (sim ? d1 : d2) + 1e-6f;
        float val = acc / den;
        int c = h*32 + d;
        float vdv = VD[(size_t)b*102400 + (size_t)n*256 + c];
        float gg  = QG[((size_t)(b*NTOK + n))*512 + 256 + c];
        OUT2[tokbase + c] = (val + vdv) * gg;
        __syncwarp();
    }
}

// ---------------- block reduce helper ----------------
__device__ __forceinline__ float blk_sum256(float v, volatile float* sw) {
    int t = threadIdx.x;
#pragma unroll
    for (int off = 16; off; off >>= 1) v += __shfl_xor_sync(0xffffffffu, v, off);
    __syncthreads();
    if ((t & 31) == 0) sw[t >> 5] = v;
    __syncthreads();
    return sw[0]+sw[1]+sw[2]+sw[3]+sw[4]+sw[5]+sw[6]+sw[7];
}

// ---------------- channel layernorm over C per token, out token-major ----------------
__global__ void k_ln(const float* __restrict__ X1, const float* __restrict__ X2,
                     const float* __restrict__ w, const float* __restrict__ bb,
                     float* __restrict__ OUT) {
    __shared__ float shm[8];
    int tk = blockIdx.x, c = threadIdx.x;
    size_t base = (size_t)tk * 256;
    float v = X1[base + c] + X2[base + c];
    float mean = blk_sum256(v, shm) * (1.0f/256.0f);
    float dv = v - mean;
    __syncthreads();
    float var = blk_sum256(dv*dv, shm) * (1.0f/256.0f);
    OUT[base + c] = w[c] * dv * rsqrtf(var + 1e-6f) + bb[c];
}

// ---------------- SE: sigmoid(se_w @ mean_spatial(src)) ----------------
__global__ void k_se(const float* __restrict__ src, const float* __restrict__ sew,
                     float* __restrict__ SE) {
    int b = blockIdx.x, t = threadIdx.x, w = t >> 5, lane = t & 31;
    __shared__ float sm[256];
    for (int ci = 0; ci < 32; ci++) {
        int c = w*32 + ci;
        const float* p = src + (size_t)b*102400 + (size_t)c*400;
        float s = 0.f;
        for (int n = lane; n < 400; n += 32) s += p[n];
#pragma unroll
        for (int off = 16; off; off >>= 1) s += __shfl_xor_sync(0xffffffffu, s, off);
        if (lane == 0) sm[c] = s * (1.0f/400.0f);
    }
    __syncthreads();
    for (int o = t; o < 512; o += 256) {
        const float* wr = sew + (size_t)o*256;
        float acc = 0.f;
        for (int c = 0; c < 256; c++) acc += wr[c] * sm[c];
        SE[(size_t)b*512 + o] = 1.0f / (1.0f + expf(-acc));
    }
}

// ---------------- depthwise 3x3 + GLU(gelu) + SE scale ----------------
__global__ __launch_bounds__(256)
void k_dw_glu(const float* __restrict__ Y, const float* __restrict__ dww,
              const float* __restrict__ SE, float* __restrict__ Y2) {
    int y = blockIdx.x, b = blockIdx.y;
    int t = threadIdx.x;
    for (int idx = t; idx < 20*512; idx += 256) {
        int x = idx >> 9, ch = idx & 511;
        float s1 = 0.f, s2 = 0.f;
#pragma unroll
        for (int ky = 0; ky < 3; ky++) {
            int yy = y + ky - 1;
            if (yy < 0 || yy >= 20) continue;
#pragma unroll
            for (int kx = 0; kx < 3; kx++) {
                int xx = x + kx - 1;
                if (xx < 0 || xx >= 20) continue;
                size_t ib = ((size_t)(b*NTOK + yy*20 + xx)) * 1024;
                s1 += Y[ib + ch]       * dww[ch*9 + ky*3 + kx];
                s2 += Y[ib + 512 + ch] * dww[(ch + 512)*9 + ky*3 + kx];
            }
        }
        float ge = 0.5f * s1 * (1.0f + erff(s1 * 0.70710678118654752f));
        Y2[((size_t)(b*NTOK + y*20 + x))*512 + ch] = ge * s2 * SE[(size_t)b*512 + ch];
    }
}

// ---------------- launcher ----------------
extern "C" void kernel_launch(void* const* d_in, const int* in_sizes, int n_in,
                              void* d_out, int out_size) {
    const float* src    = (const float*)d_in[0];
    const float* qg_w   = (const float*)d_in[1];
    const float* qg_b   = (const float*)d_in[2];
    const float* kv_w   = (const float*)d_in[3];
    const float* kv_b   = (const float*)d_in[4];
    const float* proj_w = (const float*)d_in[5];
    const float* proj_b = (const float*)d_in[6];
    const float* dwc_w  = (const float*)d_in[7];
    const float* dwc_b  = (const float*)d_in[8];
    const float* power  = (const float*)d_in[9];
    const float* scale  = (const float*)d_in[10];
    const float* pos    = (const float*)d_in[11];
    const float* pin_w  = (const float*)d_in[12];
    const float* dw_w   = (const float*)d_in[13];
    const float* se_w   = (const float*)d_in[14];
    const float* pout_w = (const float*)d_in[15];
    const float* ln1_w  = (const float*)d_in[16];
    const float* ln1_b  = (const float*)d_in[17];
    const float* ln2_w  = (const float*)d_in[18];
    const float* ln2_b  = (const float*)d_in[19];
    float* out = (float*)d_out;

    float* scr = nullptr;
    cudaGetSymbolAddress((void**)&scr, d_scratch);

    float* XT   = scr + O_XT;
    float* QG   = scr + O_QG;
    float* KV   = scr + O_KV;
    float* QP   = scr + O_QP;
    float* QN   = scr + O_QN;
    float* KP   = scr + O_KP;
    float* KN   = scr + O_KN;
    float* V    = scr + O_V;
    float* VD   = scr + O_VD;
    float* KM   = scr + O_KM;
    float* KVS  = scr + O_KVS;
    float* KVO  = scr + O_KVO;
    float* OUT2 = scr + O_OUT2;
    float* A    = scr + O_A;
    float* S    = scr + O_S;
    float* Y    = scr + O_Y;
    float* Y2   = scr + O_Y2;
    float* F    = scr + O_F;
    float* TMP  = scr + O_TMP;
    float* SE   = scr + O_SE;
    float* INV  = scr + O_INV;
    float* PW   = scr + O_PW;

    static bool attr_set = false;
    if (!attr_set) {
        cudaFuncSetAttribute(gemm_mma<3>, cudaFuncAttributeMaxDynamicSharedMemorySize, SMEM_GEMM);
        cudaFuncSetAttribute(gemm_mma<1>, cudaFuncAttributeMaxDynamicSharedMemorySize, SMEM_GEMM);
        attr_set = true;
    }

    // 1. params
    k_prep<<<1, 256>>>(scale, power, INV, PW);
    // 2. src -> token-major
    k_tr_src<<<dim3(13, 8, BATCH), dim3(32, 32)>>>(src, XT);
    // 3. qg / kv GEMMs (3xTF32 — feed the pow path, need near-fp32)
    gemm_mma<3><<<dim3(4, 200), 256, SMEM_GEMM>>>(XT, qg_w, qg_b, QG, TOKS, 512, 256);
    gemm_mma<3><<<dim3(4, 200), 256, SMEM_GEMM>>>(XT, kv_w, kv_b, KV, TOKS, 512, 256);
    // 4. pow activations + V extract
    k_attn_prep<<<TOKS, 256>>>(QG, KV, pos, INV, PW, QP, QN, KP, KN, V);
    // 5. per-(b,h) reductions
    k_reduce<<<512, 256>>>(KP, KN, V, KM, KVS, KVO);
    // 6. depthwise 5x5 on reinterpreted v
    k_dwc<<<1024, 256>>>(V, dwc_w, dwc_b, VD);
    // 7. attention output + vd + gate
    k_attn_out<<<512, 256>>>(QP, QN, KM, KVS, KVO, VD, QG, OUT2);
    // 8. projection (1xTF32 — feeds LN)
    gemm_mma<1><<<dim3(2, 200), 256, SMEM_GEMM>>>(OUT2, proj_w, proj_b, A, TOKS, 256, 256);
    // 9. LN1: s = LN(src + a)
    k_ln<<<TOKS, 256>>>(XT, A, ln1_w, ln1_b, S);
    // 10. SE gate from raw src
    k_se<<<BATCH, 256>>>(src, se_w, SE);
    // 11. pin 1x1 (1xTF32)
    gemm_mma<1><<<dim3(8, 200), 256, SMEM_GEMM>>>(S, pin_w, nullptr, Y, TOKS, 1024, 256);
    // 12. dw 3x3 + glu + se
    k_dw_glu<<<dim3(20, BATCH), 256>>>(Y, dw_w, SE, Y2);
    // 13. pout 1x1 (1xTF32)
    gemm_mma<1><<<dim3(2, 200), 256, SMEM_GEMM>>>(Y2, pout_w, nullptr, F, TOKS, 256, 512);
    // 14. LN2
    k_ln<<<TOKS, 256>>>(S, F, ln2_w, ln2_b, TMP);
    // 15. transpose to NCHW output
    k_tr_out<<<dim3(13, 8, BATCH), dim3(32, 32)>>>(TMP, out);
}

// round 4
// speedup vs baseline: 1.6017x; 1.0143x over previous
#include <cuda_runtime.h>
#include <math.h>
#include <stdint.h>

// ---------------- problem constants ----------------
#define BATCH 64
#define CCH   256          // C
#define HH    20
#define WW    20
#define NTOK  400          // H*W
#define NHEAD 8
#define HD    32           // C / heads
#define TOKS  (BATCH*NTOK) // 25600

// ---------------- scratch layout (floats) ----------------
constexpr size_t O_XT   = 0;                         // (B,N,C) src token-major
constexpr size_t O_G    = O_XT   + (size_t)TOKS*256; // (B,N,256) gate
constexpr size_t O_QP   = O_G    + (size_t)TOKS*256;
constexpr size_t O_QN   = O_QP   + (size_t)TOKS*256;
constexpr size_t O_KP   = O_QN   + (size_t)TOKS*256;
constexpr size_t O_KN   = O_KP   + (size_t)TOKS*256;
constexpr size_t O_V    = O_KN   + (size_t)TOKS*256;
constexpr size_t O_VD   = O_V    + (size_t)TOKS*256;
constexpr size_t O_KM   = O_VD   + (size_t)TOKS*256; // (B*8, 64)
constexpr size_t O_KVS  = O_KM   + (size_t)512*64;   // (B*8, 64,16)
constexpr size_t O_KVO  = O_KVS  + (size_t)512*1024;
constexpr size_t O_OUT2 = O_KVO  + (size_t)512*1024; // (B,N,C)
constexpr size_t O_S    = O_OUT2 + (size_t)TOKS*256;
constexpr size_t O_Y    = O_S    + (size_t)TOKS*256; // (B,N,1024)
constexpr size_t O_Y2   = O_Y    + (size_t)TOKS*1024;// (B,N,512)
constexpr size_t O_TMP  = O_Y2   + (size_t)TOKS*512;
constexpr size_t O_SE   = O_TMP  + (size_t)TOKS*256; // (B,512)
constexpr size_t O_INV  = O_SE   + (size_t)BATCH*512;// 256
constexpr size_t O_PW   = O_INV  + 256;              // 256
constexpr size_t SCR_TOTAL = O_PW + 256;

__device__ __align__(256) float d_scratch[SCR_TOTAL];

// =======================================================================
// helpers
// =======================================================================
__device__ __forceinline__ uint32_t smem_u32(const void* p) {
    uint32_t a;
    asm("{ .reg .u64 t; cvta.to.shared.u64 t, %1; cvt.u32.u64 %0, t; }" : "=r"(a) : "l"(p));
    return a;
}
__device__ __forceinline__ uint32_t f2tf32(float x) {
    uint32_t u; asm("cvt.rna.tf32.f32 %0, %1;" : "=r"(u) : "f"(x)); return u;
}
__device__ __forceinline__ void cp16(uint32_t s, const void* g) {
    asm volatile("cp.async.ca.shared.global [%0], [%1], 16;" :: "r"(s), "l"(g));
}
#define CP_COMMIT() asm volatile("cp.async.commit_group;" ::: "memory")
#define CP_WAIT(n)  asm volatile("cp.async.wait_group %0;" :: "n"(n) : "memory")

__device__ __forceinline__ void mma_tf32(float* d, const uint32_t* a, const uint32_t* b) {
    asm volatile(
        "mma.sync.aligned.m16n8k8.row.col.f32.tf32.tf32.f32 "
        "{%0,%1,%2,%3}, {%4,%5,%6,%7}, {%8,%9}, {%0,%1,%2,%3};"
        : "+f"(d[0]), "+f"(d[1]), "+f"(d[2]), "+f"(d[3])
        : "r"(a[0]), "r"(a[1]), "r"(a[2]), "r"(a[3]), "r"(b[0]), "r"(b[1]));
}

// =======================================================================
// gemm_mma: C[m,n] = sum_k A[m,k]*B[n,k] (+bias[n]); 128x128 CTA tile.
// SPLIT==3: 3xTF32 error compensation; SPLIT==1: plain tf32.
// EPI: 0 = write C (+bias); 1 = qg epilogue (QP/QN/G); 2 = kv epilogue (KP/KN/V).
// =======================================================================
constexpr int GS_ROW   = 36;
constexpr int GS_TILE  = 128 * GS_ROW;
constexpr int GS_BUF   = 2 * GS_TILE;
constexpr int SMEM_GEMM = 2 * GS_BUF * 4;     // 73728 bytes

template<int SPLIT, int EPI>
__global__ __launch_bounds__(256, 2)
void gemm_mma(const float* __restrict__ A, const float* __restrict__ Bw,
              const float* __restrict__ bias, float* __restrict__ C,
              int M, int N, int K,
              const float* __restrict__ invsc, const float* __restrict__ pw,
              const float* __restrict__ pos,
              float* __restrict__ P1, float* __restrict__ P2, float* __restrict__ P3) {
    extern __shared__ float sm[];
    const uint32_t sbase = smem_u32(sm);
    const int t = threadIdx.x, lane = t & 31, wid = t >> 5;
    const int wm = (wid >> 2) * 64;
    const int wn = (wid & 3) * 32;
    const int bm = blockIdx.y * 128, bn = blockIdx.x * 128;
    const int g4 = lane >> 2, l4 = lane & 3;
    const int NC = K >> 5;

    auto load_chunk = [&](int ch, int buf) {
        int k0 = ch << 5;
        uint32_t sb = sbase + (uint32_t)buf * (GS_BUF * 4);
#pragma unroll
        for (int i = 0; i < 8; i++) {
            int o = t + i * 256;
            int isB = o >> 10;
            int row = (o & 1023) >> 3;
            int seg = o & 7;
            const float* g = (isB ? Bw + (size_t)(bn + row) * K
                                  : A  + (size_t)(bm + row) * K) + k0 + seg * 4;
            uint32_t s = sb + (uint32_t)(isB * (GS_TILE * 4) + row * (GS_ROW * 4) + seg * 16);
            cp16(s, g);
        }
        CP_COMMIT();
    };

    float acc[4][4][4];
#pragma unroll
    for (int mi = 0; mi < 4; mi++)
#pragma unroll
        for (int ni = 0; ni < 4; ni++)
#pragma unroll
            for (int k = 0; k < 4; k++) acc[mi][ni][k] = 0.0f;

    load_chunk(0, 0);
    if (NC > 1) load_chunk(1, 1);

    for (int ch = 0; ch < NC; ch++) {
        if (ch + 1 < NC) { CP_WAIT(1); } else { CP_WAIT(0); }
        __syncthreads();
        const float* Ab = sm + (ch & 1) * GS_BUF;
        const float* Bb = Ab + GS_TILE;
#pragma unroll
        for (int s = 0; s < 4; s++) {
            int c0 = s * 8 + l4;
            uint32_t ah[4][4], al[4][4];
            uint32_t bh[4][2], bl[4][2];
#pragma unroll
            for (int mi = 0; mi < 4; mi++) {
                const float* ap = Ab + (wm + mi * 16 + g4) * GS_ROW;
                float x0 = ap[c0], x1 = ap[8 * GS_ROW + c0];
                float x2 = ap[c0 + 4], x3 = ap[8 * GS_ROW + c0 + 4];
                ah[mi][0] = f2tf32(x0); ah[mi][1] = f2tf32(x1);
                ah[mi][2] = f2tf32(x2); ah[mi][3] = f2tf32(x3);
                if (SPLIT == 3) {
                    al[mi][0] = f2tf32(x0 - __uint_as_float(ah[mi][0]));
                    al[mi][1] = f2tf32(x1 - __uint_as_float(ah[mi][1]));
                    al[mi][2] = f2tf32(x2 - __uint_as_float(ah[mi][2]));
                    al[mi][3] = f2tf32(x3 - __uint_as_float(ah[mi][3]));
                }
            }
#pragma unroll
            for (int ni = 0; ni < 4; ni++) {
                const float* bp = Bb + (wn + ni * 8 + g4) * GS_ROW;
                float y0 = bp[c0], y1 = bp[c0 + 4];
                bh[ni][0] = f2tf32(y0); bh[ni][1] = f2tf32(y1);
                if (SPLIT == 3) {
                    bl[ni][0] = f2tf32(y0 - __uint_as_float(bh[ni][0]));
                    bl[ni][1] = f2tf32(y1 - __uint_as_float(bh[ni][1]));
                }
            }
#pragma unroll
            for (int mi = 0; mi < 4; mi++)
#pragma unroll
                for (int ni = 0; ni < 4; ni++) {
                    mma_tf32(acc[mi][ni], ah[mi], bh[ni]);
                    if (SPLIT == 3) {
                        mma_tf32(acc[mi][ni], ah[mi], bl[ni]);
                        mma_tf32(acc[mi][ni], al[mi], bh[ni]);
                    }
                }
        }
        __syncthreads();
        if (ch + 2 < NC) load_chunk(ch + 2, ch & 1);
    }

    if (EPI == 0) {
#pragma unroll
        for (int mi = 0; mi < 4; mi++) {
            int r0 = bm + wm + mi * 16 + g4;
#pragma unroll
            for (int ni = 0; ni < 4; ni++) {
                int cb = bn + wn + ni * 8 + 2 * l4;
                float b0 = 0.f, b1 = 0.f;
                if (bias) { b0 = bias[cb]; b1 = bias[cb + 1]; }
                float2 v0 = make_float2(acc[mi][ni][0] + b0, acc[mi][ni][1] + b1);
                float2 v1 = make_float2(acc[mi][ni][2] + b0, acc[mi][ni][3] + b1);
                *(float2*)&C[(size_t)r0 * N + cb]       = v0;
                *(float2*)&C[(size_t)(r0 + 8) * N + cb] = v1;
            }
        }
    } else {
        // bn tile is uniformly either the first (channels) or second half
        bool first_half = (bn < 256);
#pragma unroll
        for (int mi = 0; mi < 4; mi++) {
#pragma unroll
            for (int half = 0; half < 2; half++) {
                int r = bm + wm + mi * 16 + g4 + half * 8;
                int tok = r % NTOK;
#pragma unroll
                for (int ni = 0; ni < 4; ni++) {
#pragma unroll
                    for (int j = 0; j < 2; j++) {
                        int ccol = bn + wn + ni * 8 + 2 * l4 + j;
                        float v = acc[mi][ni][half * 2 + j] + bias[ccol];
                        if (first_half) {
                            float x = (EPI == 2)
                                ? (v + pos[(size_t)tok * 256 + ccol]) * invsc[ccol]
                                : v * invsc[ccol];
                            float p = pw[ccol];
                            float xp = 0.f, xn = 0.f;
                            if (x > 0.f)      xp = __powf(fmaxf(x, 1e-30f), p);
                            else if (x < 0.f) xn = __powf(fmaxf(-x, 1e-30f), p);
                            P1[(size_t)r * 256 + ccol] = xp;
                            P2[(size_t)r * 256 + ccol] = xn;
                        } else {
                            P3[(size_t)r * 256 + (ccol - 256)] = v;
                        }
                    }
                }
            }
        }
    }
}

// =======================================================================
// gemm_ln: OUT = LN( RES + A@Bw^T (+bias) )  — N fixed 256, 512 threads.
// CTA tile 128 x 256. KD = 256 or 512.
// =======================================================================
constexpr int LROW = 36;
constexpr int LTA  = 128 * LROW;          // A tile floats
constexpr int LBUF = (128 + 256) * LROW;  // A + B tile floats
constexpr int SMEM_GLN = 2 * LBUF * 4;    // 110592 bytes

template<int KD>
__global__ __launch_bounds__(512)
void gemm_ln(const float* __restrict__ A, const float* __restrict__ Bw,
             const float* __restrict__ bias, const float* __restrict__ RES,
             const float* __restrict__ lw, const float* __restrict__ lb,
             float* __restrict__ OUT) {
    const int N = 256;
    extern __shared__ float sm[];
    const uint32_t sbase = smem_u32(sm);
    const int t = threadIdx.x, lane = t & 31, wid = t >> 5;
    const int wm = (wid >> 2) * 32;        // 0,32,64,96
    const int wn = (wid & 3) * 64;         // 0,64,128,192
    const int bm = blockIdx.x * 128;
    const int g4 = lane >> 2, l4 = lane & 3;
    const int NC = KD >> 5;

    auto load_chunk = [&](int ch, int buf) {
        int k0 = ch << 5;
        uint32_t sb = sbase + (uint32_t)buf * (LBUF * 4);
#pragma unroll
        for (int i = 0; i < 6; i++) {
            int o = t + i * 512;           // 0..3071
            bool isB = o >= 1024;
            int row = isB ? ((o - 1024) >> 3) : (o >> 3);
            int seg = o & 7;
            const float* g = (isB ? Bw + (size_t)row * KD
                                  : A  + (size_t)(bm + row) * KD) + k0 + seg * 4;
            uint32_t s = sb + (uint32_t)((isB ? (LTA + row * LROW) : (row * LROW)) * 4 + seg * 16);
            cp16(s, g);
        }
        CP_COMMIT();
    };

    float acc[2][8][4];
#pragma unroll
    for (int mi = 0; mi < 2; mi++)
#pragma unroll
        for (int ni = 0; ni < 8; ni++)
#pragma unroll
            for (int k = 0; k < 4; k++) acc[mi][ni][k] = 0.0f;

    load_chunk(0, 0);
    load_chunk(1, 1);

    for (int ch = 0; ch < NC; ch++) {
        if (ch + 1 < NC) { CP_WAIT(1); } else { CP_WAIT(0); }
        __syncthreads();
        const float* Ab = sm + (ch & 1) * LBUF;
        const float* Bb = Ab + LTA;
#pragma unroll
        for (int s = 0; s < 4; s++) {
            int c0 = s * 8 + l4;
            uint32_t af[2][4], bf[8][2];
#pragma unroll
            for (int mi = 0; mi < 2; mi++) {
                const float* ap = Ab + (wm + mi * 16 + g4) * LROW;
                af[mi][0] = f2tf32(ap[c0]);
                af[mi][1] = f2tf32(ap[8 * LROW + c0]);
                af[mi][2] = f2tf32(ap[c0 + 4]);
                af[mi][3] = f2tf32(ap[8 * LROW + c0 + 4]);
            }
#pragma unroll
            for (int ni = 0; ni < 8; ni++) {
                const float* bp = Bb + (wn + ni * 8 + g4) * LROW;
                bf[ni][0] = f2tf32(bp[c0]);
                bf[ni][1] = f2tf32(bp[c0 + 4]);
            }
#pragma unroll
            for (int mi = 0; mi < 2; mi++)
#pragma unroll
                for (int ni = 0; ni < 8; ni++)
                    mma_tf32(acc[mi][ni], af[mi], bf[ni]);
        }
        __syncthreads();
        if (ch + 2 < NC) load_chunk(ch + 2, ch & 1);
    }

    // ---- epilogue: bias + residual, LN over 256 cols ----
    __syncthreads();                 // tiles dead; reuse smem for reductions
    float* ssum = sm;                // [4 nwarps][128 rows]
    float* ssq  = sm + 512;

#pragma unroll
    for (int mi = 0; mi < 2; mi++)
#pragma unroll
        for (int half = 0; half < 2; half++) {
            int r = bm + wm + mi * 16 + g4 + half * 8;
#pragma unroll
            for (int ni = 0; ni < 8; ni++)
#pragma unroll
                for (int j = 0; j < 2; j++) {
                    int c = wn + ni * 8 + 2 * l4 + j;
                    float b = bias ? bias[c] : 0.f;
                    acc[mi][ni][half * 2 + j] += b + RES[(size_t)r * N + c];
                }
        }
#pragma unroll
    for (int mi = 0; mi < 2; mi++)
#pragma unroll
        for (int half = 0; half < 2; half++) {
            float s = 0.f, q = 0.f;
#pragma unroll
            for (int ni = 0; ni < 8; ni++)
#pragma unroll
                for (int j = 0; j < 2; j++) {
                    float v = acc[mi][ni][half * 2 + j];
                    s += v; q += v * v;
                }
            s += __shfl_xor_sync(0xffffffffu, s, 1);
            s += __shfl_xor_sync(0xffffffffu, s, 2);
            q += __shfl_xor_sync(0xffffffffu, q, 1);
            q += __shfl_xor_sync(0xffffffffu, q, 2);
            if (l4 == 0) {
                int lr = wm + mi * 16 + g4 + half * 8;
                ssum[(wid & 3) * 128 + lr] = s;
                ssq[(wid & 3) * 128 + lr]  = q;
            }
        }
    __syncthreads();
#pragma unroll
    for (int mi = 0; mi < 2; mi++)
#pragma unroll
        for (int half = 0; half < 2; half++) {
            int lr = wm + mi * 16 + g4 + half * 8;
            float s = ssum[lr] + ssum[128 + lr] + ssum[256 + lr] + ssum[384 + lr];
            float q = ssq[lr]  + ssq[128 + lr]  + ssq[256 + lr]  + ssq[384 + lr];
            float mean = s * (1.0f / 256.0f);
            float var  = q * (1.0f / 256.0f) - mean * mean;
            float inv  = rsqrtf(var + 1e-6f);
            int r = bm + lr;
#pragma unroll
            for (int ni = 0; ni < 8; ni++)
#pragma unroll
                for (int j = 0; j < 2; j++) {
                    int c = wn + ni * 8 + 2 * l4 + j;
                    float v = acc[mi][ni][half * 2 + j];
                    OUT[(size_t)r * N + c] = lw[c] * (v - mean) * inv + lb[c];
                }
        }
}

// ---------------- small param prep ----------------
__global__ void k_prep(const float* __restrict__ scale, const float* __restrict__ power,
                       float* __restrict__ invsc, float* __restrict__ pw) {
    int c = threadIdx.x;
    float sp = log1pf(expf(scale[c]));
    invsc[c] = 1.0f / sp;
    pw[c] = 1.0f + 4.0f / (1.0f + expf(-power[c]));
}

// ---------------- transpose (B,C,400) -> (B,400,C) ----------------
__global__ void k_tr_src(const float* __restrict__ src, float* __restrict__ XT) {
    __shared__ float tile[32][33];
    int b = blockIdx.z, cb = blockIdx.y * 32, nb = blockIdx.x * 32;
    int tx = threadIdx.x, ty = threadIdx.y;
    int n = nb + tx, c = cb + ty;
    if (n < NTOK) tile[ty][tx] = src[(size_t)b*CCH*NTOK + (size_t)c*NTOK + n];
    __syncthreads();
    n = nb + ty; c = cb + tx;
    if (n < NTOK) XT[((size_t)b*NTOK + n)*CCH + c] = tile[tx][ty];
}

// ---------------- transpose (B,400,C) -> (B,C,400) ----------------
__global__ void k_tr_out(const float* __restrict__ TMP, float* __restrict__ OUT) {
    __shared__ float tile[32][33];
    int b = blockIdx.z, cb = blockIdx.y * 32, nb = blockIdx.x * 32;
    int tx = threadIdx.x, ty = threadIdx.y;
    int n = nb + ty, c = cb + tx;
    if (n < NTOK) tile[ty][tx] = TMP[((size_t)b*NTOK + n)*CCH + c];
    __syncthreads();
    c = cb + ty; n = nb + tx;
    if (n < NTOK) OUT[(size_t)b*CCH*NTOK + (size_t)c*NTOK + n] = tile[tx][ty];
}

// ---------------- per-(b,h): k_mean(64), kv_sim(64x16), kv_opp(64x16) ----------------
__global__ __launch_bounds__(256)
void k_reduce(const float* __restrict__ KP, const float* __restrict__ KN,
              const float* __restrict__ V,
              float* __restrict__ KM, float* __restrict__ KVS, float* __restrict__ KVO) {
    int bh = blockIdx.x, b = bh >> 3, h = bh & 7;
    __shared__ float kc_s[16][64];
    __shared__ float v_s[16][32];
    int t = threadIdx.x;
    int j = t >> 2, e0 = (t & 3) << 2;
    float accs[4] = {0,0,0,0}, acco[4] = {0,0,0,0}, accm = 0.f;

    for (int n0 = 0; n0 < NTOK; n0 += 16) {
        for (int idx = t; idx < 16*64; idx += 256) {
            int nl = idx >> 6, jj = idx & 63;
            size_t base = ((size_t)(b*NTOK + n0 + nl))*256 + h*32 + (jj & 31);
            kc_s[nl][jj] = (jj < 32) ? KP[base] : KN[base];
        }
        for (int idx = t; idx < 16*32; idx += 256) {
            int nl = idx >> 5, ee = idx & 31;
            size_t base = ((size_t)(b*NTOK + n0 + nl))*256 + (ee < 16 ? h*16 + ee : 128 + h*16 + ee - 16);
            v_s[nl][ee] = V[base];
        }
        __syncthreads();
#pragma unroll
        for (int nl = 0; nl < 16; nl++) {
            float kcv = kc_s[nl][j];
            accm += kcv;
#pragma unroll
            for (int q = 0; q < 4; q++) {
                accs[q] += kcv * v_s[nl][e0 + q];
                acco[q] += kcv * v_s[nl][16 + e0 + q];
            }
        }
        __syncthreads();
    }
    const float invN = 1.0f / (float)NTOK;
    size_t ob = (size_t)bh*1024 + (size_t)j*16 + e0;
#pragma unroll
    for (int q = 0; q < 4; q++) { KVS[ob+q] = accs[q]*invN; KVO[ob+q] = acco[q]*invN; }
    if ((t & 3) == 0) KM[(size_t)bh*64 + j] = accm * invN;
}

// ---------------- depthwise 5x5 on reinterpreted v ----------------
__global__ __launch_bounds__(256)
void k_dwc(const float* __restrict__ V, const float* __restrict__ w,
           const float* __restrict__ bias, float* __restrict__ VD) {
    __shared__ float tile[14*640];
    __shared__ float ws[800];
    __shared__ float bs[32];
    int blk = blockIdx.x;
    int half = blk & 1, g = (blk >> 1) & 7, b = blk >> 4;
    int t = threadIdx.x;
    for (int i = t; i < 800; i += 256) ws[i] = w[i];
    if (t < 32) bs[t] = bias[t];
    const float* Vb = V + (size_t)b*102400 + (size_t)g*12800;
    int r0 = half*10 - 2;
    for (int i = t; i < 14*640; i += 256) {
        int rr = i / 640, rem = i - rr*640;
        int r = r0 + rr;
        tile[i] = (r >= 0 && r < 20) ? Vb[r*640 + rem] : 0.0f;
    }
    __syncthreads();
    for (int oi = t; oi < 10*640; oi += 256) {
        int yl = oi / 640, rem = oi - yl*640;
        int x = rem >> 5, dd = rem & 31;
        int lrow = yl + 2;
        float acc = bs[dd];
#pragma unroll
        for (int ky = 0; ky < 5; ky++) {
#pragma unroll
            for (int kx = 0; kx < 5; kx++) {
                int xx = x + kx - 2;
                if (xx >= 0 && xx < 20)
                    acc += tile[(lrow + ky - 2)*640 + xx*32 + dd] * ws[dd*25 + ky*5 + kx];
            }
        }
        int y = half*10 + yl;
        VD[(size_t)b*102400 + (size_t)g*12800 + (size_t)y*640 + rem] = acc;
    }
}

// ---------------- attention output + vd + gate ----------------
__global__ __launch_bounds__(256)
void k_attn_out(const float* __restrict__ QP, const float* __restrict__ QN,
                const float* __restrict__ KM, const float* __restrict__ KVS,
                const float* __restrict__ KVO, const float* __restrict__ VD,
                const float* __restrict__ G, float* __restrict__ OUT2) {
    int bh = blockIdx.x, b = bh >> 3, h = bh & 7;
    __shared__ float km_s[64];
    __shared__ float kvb[64][32];
    __shared__ float qps[8][32], qns[8][32];
    int t = threadIdx.x, w = t >> 5, d = t & 31;
    for (int idx = t; idx < 64; idx += 256) km_s[idx] = KM[(size_t)bh*64 + idx];
    for (int idx = t; idx < 2048; idx += 256) {
        int j = idx >> 5, col = idx & 31;
        kvb[j][col] = (col < 16) ? KVS[(size_t)bh*1024 + j*16 + col]
                                 : KVO[(size_t)bh*1024 + j*16 + (col - 16)];
    }
    __syncthreads();
    bool sim = (d < 16);
    for (int n0 = 0; n0 < NTOK; n0 += 8) {
        int n = n0 + w;
        size_t tokbase = ((size_t)(b*NTOK + n)) * 256;
        float qp = QP[tokbase + h*32 + d];
        float qn = QN[tokbase + h*32 + d];
        qps[w][d] = qp; qns[w][d] = qn;
        __syncwarp();
        float d1 = qp*km_s[d] + qn*km_s[32 + d];
        float d2 = qn*km_s[d] + qp*km_s[32 + d];
#pragma unroll
        for (int off = 16; off; off >>= 1) {
            d1 += __shfl_xor_sync(0xffffffffu, d1, off);
            d2 += __shfl_xor_sync(0xffffffffu, d2, off);
        }
        float acc = 0.f;
#pragma unroll
        for (int j = 0; j < 32; j++) {
            float a = qps[w][j], bb = qns[w][j];
            float m1 = sim ? a : bb;
            float m2 = sim ? bb : a;
            acc += m1*kvb[j][d] + m2*kvb[32 + j][d];
        }
        float den = (sim ? d1 : d2) + 1e-6f;
        float val = acc / den;
        int c = h*32 + d;
        float vdv = VD[(size_t)b*102400 + (size_t)n*256 + c];
        float gg  = G[tokbase + c];
        OUT2[tokbase + c] = (val + vdv) * gg;
        __syncwarp();
    }
}

// ---------------- SE: sigmoid(se_w @ mean_spatial(src)) ----------------
__global__ void k_se(const float* __restrict__ src, const float* __restrict__ sew,
                     float* __restrict__ SE) {
    int b = blockIdx.x, t = threadIdx.x, w = t >> 5, lane = t & 31;
    __shared__ float sm[256];
    for (int ci = 0; ci < 32; ci++) {
        int c = w*32 + ci;
        const float* p = src + (size_t)b*102400 + (size_t)c*400;
        float s = 0.f;
        for (int n = lane; n < 400; n += 32) s += p[n];
#pragma unroll
        for (int off = 16; off; off >>= 1) s += __shfl_xor_sync(0xffffffffu, s, off);
        if (lane == 0) sm[c] = s * (1.0f/400.0f);
    }
    __syncthreads();
    for (int o = t; o < 512; o += 256) {
        const float* wr = sew + (size_t)o*256;
        float acc = 0.f;
        for (int c = 0; c < 256; c++) acc += wr[c] * sm[c];
        SE[(size_t)b*512 + o] = 1.0f / (1.0f + expf(-acc));
    }
}

// ---------------- depthwise 3x3 + GLU(gelu) + SE scale ----------------
__global__ __launch_bounds__(256)
void k_dw_glu(const float* __restrict__ Y, const float* __restrict__ dww,
              const float* __restrict__ SE, float* __restrict__ Y2) {
    int y = blockIdx.x, b = blockIdx.y;
    int t = threadIdx.x;
    for (int idx = t; idx < 20*512; idx += 256) {
        int x = idx >> 9, ch = idx & 511;
        float s1 = 0.f, s2 = 0.f;
#pragma unroll
        for (int ky = 0; ky < 3; ky++) {
            int yy = y + ky - 1;
            if (yy < 0 || yy >= 20) continue;
#pragma unroll
            for (int kx = 0; kx < 3; kx++) {
                int xx = x + kx - 1;
                if (xx < 0 || xx >= 20) continue;
                size_t ib = ((size_t)(b*NTOK + yy*20 + xx)) * 1024;
                s1 += Y[ib + ch]       * dww[ch*9 + ky*3 + kx];
                s2 += Y[ib + 512 + ch] * dww[(ch + 512)*9 + ky*3 + kx];
            }
        }
        float ge = 0.5f * s1 * (1.0f + erff(s1 * 0.70710678118654752f));
        Y2[((size_t)(b*NTOK + y*20 + x))*512 + ch] = ge * s2 * SE[(size_t)b*512 + ch];
    }
}

// ---------------- launcher ----------------
extern "C" void kernel_launch(void* const* d_in, const int* in_sizes, int n_in,
                              void* d_out, int out_size) {
    const float* src    = (const float*)d_in[0];
    const float* qg_w   = (const float*)d_in[1];
    const float* qg_b   = (const float*)d_in[2];
    const float* kv_w   = (const float*)d_in[3];
    const float* kv_b   = (const float*)d_in[4];
    const float* proj_w = (const float*)d_in[5];
    const float* proj_b = (const float*)d_in[6];
    const float* dwc_w  = (const float*)d_in[7];
    const float* dwc_b  = (const float*)d_in[8];
    const float* power  = (const float*)d_in[9];
    const float* scale  = (const float*)d_in[10];
    const float* pos    = (const float*)d_in[11];
    const float* pin_w  = (const float*)d_in[12];
    const float* dw_w   = (const float*)d_in[13];
    const float* se_w   = (const float*)d_in[14];
    const float* pout_w = (const float*)d_in[15];
    const float* ln1_w  = (const float*)d_in[16];
    const float* ln1_b  = (const float*)d_in[17];
    const float* ln2_w  = (const float*)d_in[18];
    const float* ln2_b  = (const float*)d_in[19];
    float* out = (float*)d_out;

    float* scr = nullptr;
    cudaGetSymbolAddress((void**)&scr, d_scratch);

    float* XT   = scr + O_XT;
    float* G    = scr + O_G;
    float* QP   = scr + O_QP;
    float* QN   = scr + O_QN;
    float* KP   = scr + O_KP;
    float* KN   = scr + O_KN;
    float* V    = scr + O_V;
    float* VD   = scr + O_VD;
    float* KM   = scr + O_KM;
    float* KVS  = scr + O_KVS;
    float* KVO  = scr + O_KVO;
    float* OUT2 = scr + O_OUT2;
    float* S    = scr + O_S;
    float* Y    = scr + O_Y;
    float* Y2   = scr + O_Y2;
    float* TMP  = scr + O_TMP;
    float* SE   = scr + O_SE;
    float* INV  = scr + O_INV;
    float* PW   = scr + O_PW;

    static bool attr_set = false;
    if (!attr_set) {
        cudaFuncSetAttribute(gemm_mma<3,1>, cudaFuncAttributeMaxDynamicSharedMemorySize, SMEM_GEMM);
        cudaFuncSetAttribute(gemm_mma<3,2>, cudaFuncAttributeMaxDynamicSharedMemorySize, SMEM_GEMM);
        cudaFuncSetAttribute(gemm_mma<1,0>, cudaFuncAttributeMaxDynamicSharedMemorySize, SMEM_GEMM);
        cudaFuncSetAttribute(gemm_ln<256>, cudaFuncAttributeMaxDynamicSharedMemorySize, SMEM_GLN);
        cudaFuncSetAttribute(gemm_ln<512>, cudaFuncAttributeMaxDynamicSharedMemorySize, SMEM_GLN);
        attr_set = true;
    }

    // 1. params
    k_prep<<<1, 256>>>(scale, power, INV, PW);
    // 2. src -> token-major
    k_tr_src<<<dim3(13, 8, BATCH), dim3(32, 32)>>>(src, XT);
    // 3. qg GEMM + fused pow/gate epilogue
    gemm_mma<3,1><<<dim3(4, 200), 256, SMEM_GEMM>>>(XT, qg_w, qg_b, nullptr,
        TOKS, 512, 256, INV, PW, nullptr, QP, QN, G);
    // 4. kv GEMM + fused pos/pow/V epilogue
    gemm_mma<3,2><<<dim3(4, 200), 256, SMEM_GEMM>>>(XT, kv_w, kv_b, nullptr,
        TOKS, 512, 256, INV, PW, pos, KP, KN, V);
    // 5. per-(b,h) reductions
    k_reduce<<<512, 256>>>(KP, KN, V, KM, KVS, KVO);
    // 6. depthwise 5x5 on reinterpreted v
    k_dwc<<<1024, 256>>>(V, dwc_w, dwc_b, VD);
    // 7. attention output + vd + gate
    k_attn_out<<<512, 256>>>(QP, QN, KM, KVS, KVO, VD, G, OUT2);
    // 8. proj + residual + LN1 fused
    gemm_ln<256><<<200, 512, SMEM_GLN>>>(OUT2, proj_w, proj_b, XT, ln1_w, ln1_b, S);
    // 9. SE gate from raw src
    k_se<<<BATCH, 256>>>(src, se_w, SE);
    // 10. pin 1x1
    gemm_mma<1,0><<<dim3(8, 200), 256, SMEM_GEMM>>>(S, pin_w, nullptr, Y,
        TOKS, 1024, 256, nullptr, nullptr, nullptr, nullptr, nullptr, nullptr);
    // 11. dw 3x3 + glu + se
    k_dw_glu<<<dim3(20, BATCH), 256>>>(Y, dw_w, SE, Y2);
    // 12. pout + residual + LN2 fused
    gemm_ln<512><<<200, 512, SMEM_GLN>>>(Y2, pout_w, nullptr, S, ln2_w, ln2_b, TMP);
    // 13. transpose to NCHW output
    k_tr_out<<<dim3(13, 8, BATCH), dim3(32, 32)>>>(TMP, out);
}

// round 5
// speedup vs baseline: 1.7268x; 1.0781x over previous
#include <cuda_runtime.h>
#include <math.h>
#include <stdint.h>

// ---------------- problem constants ----------------
#define BATCH 64
#define CCH   256          // C
#define HH    20
#define WW    20
#define NTOK  400          // H*W
#define NHEAD 8
#define HD    32           // C / heads
#define TOKS  (BATCH*NTOK) // 25600

// ---------------- scratch layout (floats) ----------------
constexpr size_t O_XT   = 0;                         // (B,N,C) src token-major
constexpr size_t O_G    = O_XT   + (size_t)TOKS*256; // (B,N,256) gate
constexpr size_t O_QP   = O_G    + (size_t)TOKS*256;
constexpr size_t O_QN   = O_QP   + (size_t)TOKS*256;
constexpr size_t O_KP   = O_QN   + (size_t)TOKS*256;
constexpr size_t O_KN   = O_KP   + (size_t)TOKS*256;
constexpr size_t O_V    = O_KN   + (size_t)TOKS*256;
constexpr size_t O_VD   = O_V    + (size_t)TOKS*256;
constexpr size_t O_KM   = O_VD   + (size_t)TOKS*256; // (B*8, 64)
constexpr size_t O_KVS  = O_KM   + (size_t)512*64;   // (B*8, 64,16)
constexpr size_t O_KVO  = O_KVS  + (size_t)512*1024;
constexpr size_t O_OUT2 = O_KVO  + (size_t)512*1024; // (B,N,C)
constexpr size_t O_S    = O_OUT2 + (size_t)TOKS*256;
constexpr size_t O_Y    = O_S    + (size_t)TOKS*256; // (B,N,1024)
constexpr size_t O_Y2   = O_Y    + (size_t)TOKS*1024;// (B,N,512)
constexpr size_t O_TMP  = O_Y2   + (size_t)TOKS*512;
constexpr size_t O_SE   = O_TMP  + (size_t)TOKS*256; // (B,512)
constexpr size_t O_INV  = O_SE   + (size_t)BATCH*512;// 256
constexpr size_t O_PW   = O_INV  + 256;              // 256
constexpr size_t SCR_TOTAL = O_PW + 256;

__device__ __align__(256) float d_scratch[SCR_TOTAL];

// =======================================================================
// helpers
// =======================================================================
__device__ __forceinline__ uint32_t smem_u32(const void* p) {
    uint32_t a;
    asm("{ .reg .u64 t; cvta.to.shared.u64 t, %1; cvt.u32.u64 %0, t; }" : "=r"(a) : "l"(p));
    return a;
}
__device__ __forceinline__ uint32_t f2tf32(float x) {
    uint32_t u; asm("cvt.rna.tf32.f32 %0, %1;" : "=r"(u) : "f"(x)); return u;
}
__device__ __forceinline__ void cp16(uint32_t s, const void* g) {
    asm volatile("cp.async.ca.shared.global [%0], [%1], 16;" :: "r"(s), "l"(g));
}
#define CP_COMMIT() asm volatile("cp.async.commit_group;" ::: "memory")
#define CP_WAIT(n)  asm volatile("cp.async.wait_group %0;" :: "n"(n) : "memory")

__device__ __forceinline__ void mma_tf32(float* d, const uint32_t* a, const uint32_t* b) {
    asm volatile(
        "mma.sync.aligned.m16n8k8.row.col.f32.tf32.tf32.f32 "
        "{%0,%1,%2,%3}, {%4,%5,%6,%7}, {%8,%9}, {%0,%1,%2,%3};"
        : "+f"(d[0]), "+f"(d[1]), "+f"(d[2]), "+f"(d[3])
        : "r"(a[0]), "r"(a[1]), "r"(a[2]), "r"(a[3]), "r"(b[0]), "r"(b[1]));
}

// =======================================================================
// gemm_mma: C[m,n] = sum_k A[m,k]*B[n,k] (+bias[n]); 128x128 CTA tile.
// SPLIT==3: 3xTF32 error compensation; SPLIT==1: plain tf32.
// EPI: 0 = write C (+bias); 1 = qg epilogue (QP/QN/G); 2 = kv epilogue (KP/KN/V).
// =======================================================================
constexpr int GS_ROW   = 36;
constexpr int GS_TILE  = 128 * GS_ROW;
constexpr int GS_BUF   = 2 * GS_TILE;
constexpr int SMEM_GEMM = 2 * GS_BUF * 4;     // 73728 bytes

template<int SPLIT, int EPI>
__global__ __launch_bounds__(256, 2)
void gemm_mma(const float* __restrict__ A, const float* __restrict__ Bw,
              const float* __restrict__ bias, float* __restrict__ C,
              int M, int N, int K,
              const float* __restrict__ invsc, const float* __restrict__ pw,
              const float* __restrict__ pos,
              float* __restrict__ P1, float* __restrict__ P2, float* __restrict__ P3) {
    extern __shared__ float sm[];
    const uint32_t sbase = smem_u32(sm);
    const int t = threadIdx.x, lane = t & 31, wid = t >> 5;
    const int wm = (wid >> 2) * 64;
    const int wn = (wid & 3) * 32;
    const int bm = blockIdx.y * 128, bn = blockIdx.x * 128;
    const int g4 = lane >> 2, l4 = lane & 3;
    const int NC = K >> 5;

    auto load_chunk = [&](int ch, int buf) {
        int k0 = ch << 5;
        uint32_t sb = sbase + (uint32_t)buf * (GS_BUF * 4);
#pragma unroll
        for (int i = 0; i < 8; i++) {
            int o = t + i * 256;
            int isB = o >> 10;
            int row = (o & 1023) >> 3;
            int seg = o & 7;
            const float* g = (isB ? Bw + (size_t)(bn + row) * K
                                  : A  + (size_t)(bm + row) * K) + k0 + seg * 4;
            uint32_t s = sb + (uint32_t)(isB * (GS_TILE * 4) + row * (GS_ROW * 4) + seg * 16);
            cp16(s, g);
        }
        CP_COMMIT();
    };

    float acc[4][4][4];
#pragma unroll
    for (int mi = 0; mi < 4; mi++)
#pragma unroll
        for (int ni = 0; ni < 4; ni++)
#pragma unroll
            for (int k = 0; k < 4; k++) acc[mi][ni][k] = 0.0f;

    load_chunk(0, 0);
    if (NC > 1) load_chunk(1, 1);

    for (int ch = 0; ch < NC; ch++) {
        if (ch + 1 < NC) { CP_WAIT(1); } else { CP_WAIT(0); }
        __syncthreads();
        const float* Ab = sm + (ch & 1) * GS_BUF;
        const float* Bb = Ab + GS_TILE;
#pragma unroll
        for (int s = 0; s < 4; s++) {
            int c0 = s * 8 + l4;
            uint32_t ah[4][4], al[4][4];
            uint32_t bh[4][2], bl[4][2];
#pragma unroll
            for (int mi = 0; mi < 4; mi++) {
                const float* ap = Ab + (wm + mi * 16 + g4) * GS_ROW;
                float x0 = ap[c0], x1 = ap[8 * GS_ROW + c0];
                float x2 = ap[c0 + 4], x3 = ap[8 * GS_ROW + c0 + 4];
                ah[mi][0] = f2tf32(x0); ah[mi][1] = f2tf32(x1);
                ah[mi][2] = f2tf32(x2); ah[mi][3] = f2tf32(x3);
                if (SPLIT == 3) {
                    al[mi][0] = f2tf32(x0 - __uint_as_float(ah[mi][0]));
                    al[mi][1] = f2tf32(x1 - __uint_as_float(ah[mi][1]));
                    al[mi][2] = f2tf32(x2 - __uint_as_float(ah[mi][2]));
                    al[mi][3] = f2tf32(x3 - __uint_as_float(ah[mi][3]));
                }
            }
#pragma unroll
            for (int ni = 0; ni < 4; ni++) {
                const float* bp = Bb + (wn + ni * 8 + g4) * GS_ROW;
                float y0 = bp[c0], y1 = bp[c0 + 4];
                bh[ni][0] = f2tf32(y0); bh[ni][1] = f2tf32(y1);
                if (SPLIT == 3) {
                    bl[ni][0] = f2tf32(y0 - __uint_as_float(bh[ni][0]));
                    bl[ni][1] = f2tf32(y1 - __uint_as_float(bh[ni][1]));
                }
            }
#pragma unroll
            for (int mi = 0; mi < 4; mi++)
#pragma unroll
                for (int ni = 0; ni < 4; ni++) {
                    mma_tf32(acc[mi][ni], ah[mi], bh[ni]);
                    if (SPLIT == 3) {
                        mma_tf32(acc[mi][ni], ah[mi], bl[ni]);
                        mma_tf32(acc[mi][ni], al[mi], bh[ni]);
                    }
                }
        }
        __syncthreads();
        if (ch + 2 < NC) load_chunk(ch + 2, ch & 1);
    }

    if (EPI == 0) {
#pragma unroll
        for (int mi = 0; mi < 4; mi++) {
            int r0 = bm + wm + mi * 16 + g4;
#pragma unroll
            for (int ni = 0; ni < 4; ni++) {
                int cb = bn + wn + ni * 8 + 2 * l4;
                float b0 = 0.f, b1 = 0.f;
                if (bias) { b0 = bias[cb]; b1 = bias[cb + 1]; }
                float2 v0 = make_float2(acc[mi][ni][0] + b0, acc[mi][ni][1] + b1);
                float2 v1 = make_float2(acc[mi][ni][2] + b0, acc[mi][ni][3] + b1);
                *(float2*)&C[(size_t)r0 * N + cb]       = v0;
                *(float2*)&C[(size_t)(r0 + 8) * N + cb] = v1;
            }
        }
    } else {
        bool first_half = (bn < 256);
#pragma unroll
        for (int mi = 0; mi < 4; mi++) {
#pragma unroll
            for (int half = 0; half < 2; half++) {
                int r = bm + wm + mi * 16 + g4 + half * 8;
                int tok = r % NTOK;
#pragma unroll
                for (int ni = 0; ni < 4; ni++) {
#pragma unroll
                    for (int j = 0; j < 2; j++) {
                        int ccol = bn + wn + ni * 8 + 2 * l4 + j;
                        float v = acc[mi][ni][half * 2 + j] + bias[ccol];
                        if (first_half) {
                            float x = (EPI == 2)
                                ? (v + pos[(size_t)tok * 256 + ccol]) * invsc[ccol]
                                : v * invsc[ccol];
                            float p = pw[ccol];
                            float xp = 0.f, xn = 0.f;
                            if (x > 0.f)      xp = __powf(fmaxf(x, 1e-30f), p);
                            else if (x < 0.f) xn = __powf(fmaxf(-x, 1e-30f), p);
                            P1[(size_t)r * 256 + ccol] = xp;
                            P2[(size_t)r * 256 + ccol] = xn;
                        } else {
                            P3[(size_t)r * 256 + (ccol - 256)] = v;
                        }
                    }
                }
            }
        }
    }
}

// =======================================================================
// gemm_ln: OUT = LN( RES + A@Bw^T (+bias) )  — N fixed 256, 512 threads.
// =======================================================================
constexpr int LROW = 36;
constexpr int LTA  = 128 * LROW;
constexpr int LBUF = (128 + 256) * LROW;
constexpr int SMEM_GLN = 2 * LBUF * 4;

template<int KD>
__global__ __launch_bounds__(512)
void gemm_ln(const float* __restrict__ A, const float* __restrict__ Bw,
             const float* __restrict__ bias, const float* __restrict__ RES,
             const float* __restrict__ lw, const float* __restrict__ lb,
             float* __restrict__ OUT) {
    const int N = 256;
    extern __shared__ float sm[];
    const uint32_t sbase = smem_u32(sm);
    const int t = threadIdx.x, lane = t & 31, wid = t >> 5;
    const int wm = (wid >> 2) * 32;
    const int wn = (wid & 3) * 64;
    const int bm = blockIdx.x * 128;
    const int g4 = lane >> 2, l4 = lane & 3;
    const int NC = KD >> 5;

    auto load_chunk = [&](int ch, int buf) {
        int k0 = ch << 5;
        uint32_t sb = sbase + (uint32_t)buf * (LBUF * 4);
#pragma unroll
        for (int i = 0; i < 6; i++) {
            int o = t + i * 512;
            bool isB = o >= 1024;
            int row = isB ? ((o - 1024) >> 3) : (o >> 3);
            int seg = o & 7;
            const float* g = (isB ? Bw + (size_t)row * KD
                                  : A  + (size_t)(bm + row) * KD) + k0 + seg * 4;
            uint32_t s = sb + (uint32_t)((isB ? (LTA + row * LROW) : (row * LROW)) * 4 + seg * 16);
            cp16(s, g);
        }
        CP_COMMIT();
    };

    float acc[2][8][4];
#pragma unroll
    for (int mi = 0; mi < 2; mi++)
#pragma unroll
        for (int ni = 0; ni < 8; ni++)
#pragma unroll
            for (int k = 0; k < 4; k++) acc[mi][ni][k] = 0.0f;

    load_chunk(0, 0);
    load_chunk(1, 1);

    for (int ch = 0; ch < NC; ch++) {
        if (ch + 1 < NC) { CP_WAIT(1); } else { CP_WAIT(0); }
        __syncthreads();
        const float* Ab = sm + (ch & 1) * LBUF;
        const float* Bb = Ab + LTA;
#pragma unroll
        for (int s = 0; s < 4; s++) {
            int c0 = s * 8 + l4;
            uint32_t af[2][4], bf[8][2];
#pragma unroll
            for (int mi = 0; mi < 2; mi++) {
                const float* ap = Ab + (wm + mi * 16 + g4) * LROW;
                af[mi][0] = f2tf32(ap[c0]);
                af[mi][1] = f2tf32(ap[8 * LROW + c0]);
                af[mi][2] = f2tf32(ap[c0 + 4]);
                af[mi][3] = f2tf32(ap[8 * LROW + c0 + 4]);
            }
#pragma unroll
            for (int ni = 0; ni < 8; ni++) {
                const float* bp = Bb + (wn + ni * 8 + g4) * LROW;
                bf[ni][0] = f2tf32(bp[c0]);
                bf[ni][1] = f2tf32(bp[c0 + 4]);
            }
#pragma unroll
            for (int mi = 0; mi < 2; mi++)
#pragma unroll
                for (int ni = 0; ni < 8; ni++)
                    mma_tf32(acc[mi][ni], af[mi], bf[ni]);
        }
        __syncthreads();
        if (ch + 2 < NC) load_chunk(ch + 2, ch & 1);
    }

    __syncthreads();
    float* ssum = sm;
    float* ssq  = sm + 512;

#pragma unroll
    for (int mi = 0; mi < 2; mi++)
#pragma unroll
        for (int half = 0; half < 2; half++) {
            int r = bm + wm + mi * 16 + g4 + half * 8;
#pragma unroll
            for (int ni = 0; ni < 8; ni++)
#pragma unroll
                for (int j = 0; j < 2; j++) {
                    int c = wn + ni * 8 + 2 * l4 + j;
                    float b = bias ? bias[c] : 0.f;
                    acc[mi][ni][half * 2 + j] += b + RES[(size_t)r * N + c];
                }
        }
#pragma unroll
    for (int mi = 0; mi < 2; mi++)
#pragma unroll
        for (int half = 0; half < 2; half++) {
            float s = 0.f, q = 0.f;
#pragma unroll
            for (int ni = 0; ni < 8; ni++)
#pragma unroll
                for (int j = 0; j < 2; j++) {
                    float v = acc[mi][ni][half * 2 + j];
                    s += v; q += v * v;
                }
            s += __shfl_xor_sync(0xffffffffu, s, 1);
            s += __shfl_xor_sync(0xffffffffu, s, 2);
            q += __shfl_xor_sync(0xffffffffu, q, 1);
            q += __shfl_xor_sync(0xffffffffu, q, 2);
            if (l4 == 0) {
                int lr = wm + mi * 16 + g4 + half * 8;
                ssum[(wid & 3) * 128 + lr] = s;
                ssq[(wid & 3) * 128 + lr]  = q;
            }
        }
    __syncthreads();
#pragma unroll
    for (int mi = 0; mi < 2; mi++)
#pragma unroll
        for (int half = 0; half < 2; half++) {
            int lr = wm + mi * 16 + g4 + half * 8;
            float s = ssum[lr] + ssum[128 + lr] + ssum[256 + lr] + ssum[384 + lr];
            float q = ssq[lr]  + ssq[128 + lr]  + ssq[256 + lr]  + ssq[384 + lr];
            float mean = s * (1.0f / 256.0f);
            float var  = q * (1.0f / 256.0f) - mean * mean;
            float inv  = rsqrtf(var + 1e-6f);
            int r = bm + lr;
#pragma unroll
            for (int ni = 0; ni < 8; ni++)
#pragma unroll
                for (int j = 0; j < 2; j++) {
                    int c = wn + ni * 8 + 2 * l4 + j;
                    float v = acc[mi][ni][half * 2 + j];
                    OUT[(size_t)r * N + c] = lw[c] * (v - mean) * inv + lb[c];
                }
        }
}

// ---------------- small param prep ----------------
__global__ void k_prep(const float* __restrict__ scale, const float* __restrict__ power,
                       float* __restrict__ invsc, float* __restrict__ pw) {
    int c = threadIdx.x;
    float sp = log1pf(expf(scale[c]));
    invsc[c] = 1.0f / sp;
    pw[c] = 1.0f + 4.0f / (1.0f + expf(-power[c]));
}

// ---------------- transpose (B,C,400) -> (B,400,C) ----------------
__global__ void k_tr_src(const float* __restrict__ src, float* __restrict__ XT) {
    __shared__ float tile[32][33];
    int b = blockIdx.z, cb = blockIdx.y * 32, nb = blockIdx.x * 32;
    int tx = threadIdx.x, ty = threadIdx.y;
    int n = nb + tx, c = cb + ty;
    if (n < NTOK) tile[ty][tx] = src[(size_t)b*CCH*NTOK + (size_t)c*NTOK + n];
    __syncthreads();
    n = nb + ty; c = cb + tx;
    if (n < NTOK) XT[((size_t)b*NTOK + n)*CCH + c] = tile[tx][ty];
}

// ---------------- transpose (B,400,C) -> (B,C,400) ----------------
__global__ void k_tr_out(const float* __restrict__ TMP, float* __restrict__ OUT) {
    __shared__ float tile[32][33];
    int b = blockIdx.z, cb = blockIdx.y * 32, nb = blockIdx.x * 32;
    int tx = threadIdx.x, ty = threadIdx.y;
    int n = nb + ty, c = cb + tx;
    if (n < NTOK) tile[ty][tx] = TMP[((size_t)b*NTOK + n)*CCH + c];
    __syncthreads();
    c = cb + ty; n = nb + tx;
    if (n < NTOK) OUT[(size_t)b*CCH*NTOK + (size_t)c*NTOK + n] = tile[tx][ty];
}

// ---------------- per-(b,h): k_mean(64), kv_sim(64x16), kv_opp(64x16) ----------------
__global__ __launch_bounds__(256)
void k_reduce(const float* __restrict__ KP, const float* __restrict__ KN,
              const float* __restrict__ V,
              float* __restrict__ KM, float* __restrict__ KVS, float* __restrict__ KVO) {
    int bh = blockIdx.x, b = bh >> 3, h = bh & 7;
    __shared__ float kc_s[16][64];
    __shared__ float v_s[16][32];
    int t = threadIdx.x;
    int j = t >> 2, e0 = (t & 3) << 2;
    float accs[4] = {0,0,0,0}, acco[4] = {0,0,0,0}, accm = 0.f;

    for (int n0 = 0; n0 < NTOK; n0 += 16) {
        for (int idx = t; idx < 16*64; idx += 256) {
            int nl = idx >> 6, jj = idx & 63;
            size_t base = ((size_t)(b*NTOK + n0 + nl))*256 + h*32 + (jj & 31);
            kc_s[nl][jj] = (jj < 32) ? KP[base] : KN[base];
        }
        for (int idx = t; idx < 16*32; idx += 256) {
            int nl = idx >> 5, ee = idx & 31;
            size_t base = ((size_t)(b*NTOK + n0 + nl))*256 + (ee < 16 ? h*16 + ee : 128 + h*16 + ee - 16);
            v_s[nl][ee] = V[base];
        }
        __syncthreads();
#pragma unroll
        for (int nl = 0; nl < 16; nl++) {
            float kcv = kc_s[nl][j];
            accm += kcv;
#pragma unroll
            for (int q = 0; q < 4; q++) {
                accs[q] += kcv * v_s[nl][e0 + q];
                acco[q] += kcv * v_s[nl][16 + e0 + q];
            }
        }
        __syncthreads();
    }
    const float invN = 1.0f / (float)NTOK;
    size_t ob = (size_t)bh*1024 + (size_t)j*16 + e0;
#pragma unroll
    for (int q = 0; q < 4; q++) { KVS[ob+q] = accs[q]*invN; KVO[ob+q] = acco[q]*invN; }
    if ((t & 3) == 0) KM[(size_t)bh*64 + j] = accm * invN;
}

// ---------------- depthwise 5x5 on reinterpreted v ----------------
__global__ __launch_bounds__(256)
void k_dwc(const float* __restrict__ V, const float* __restrict__ w,
           const float* __restrict__ bias, float* __restrict__ VD) {
    __shared__ float tile[14*640];
    __shared__ float ws[800];
    __shared__ float bs[32];
    int blk = blockIdx.x;
    int half = blk & 1, g = (blk >> 1) & 7, b = blk >> 4;
    int t = threadIdx.x;
    for (int i = t; i < 800; i += 256) ws[i] = w[i];
    if (t < 32) bs[t] = bias[t];
    const float* Vb = V + (size_t)b*102400 + (size_t)g*12800;
    int r0 = half*10 - 2;
    for (int i = t; i < 14*640; i += 256) {
        int rr = i / 640, rem = i - rr*640;
        int r = r0 + rr;
        tile[i] = (r >= 0 && r < 20) ? Vb[r*640 + rem] : 0.0f;
    }
    __syncthreads();
    for (int oi = t; oi < 10*640; oi += 256) {
        int yl = oi / 640, rem = oi - yl*640;
        int x = rem >> 5, dd = rem & 31;
        int lrow = yl + 2;
        float acc = bs[dd];
#pragma unroll
        for (int ky = 0; ky < 5; ky++) {
#pragma unroll
            for (int kx = 0; kx < 5; kx++) {
                int xx = x + kx - 2;
                if (xx >= 0 && xx < 20)
                    acc += tile[(lrow + ky - 2)*640 + xx*32 + dd] * ws[dd*25 + ky*5 + kx];
            }
        }
        int y = half*10 + yl;
        VD[(size_t)b*102400 + (size_t)g*12800 + (size_t)y*640 + rem] = acc;
    }
}

// ---------------- attention output + vd + gate ----------------
__global__ __launch_bounds__(256)
void k_attn_out(const float* __restrict__ QP, const float* __restrict__ QN,
                const float* __restrict__ KM, const float* __restrict__ KVS,
                const float* __restrict__ KVO, const float* __restrict__ VD,
                const float* __restrict__ G, float* __restrict__ OUT2) {
    int bh = blockIdx.x, b = bh >> 3, h = bh & 7;
    __shared__ float km_s[64];
    __shared__ float kvb[64][32];
    __shared__ float qps[8][32], qns[8][32];
    int t = threadIdx.x, w = t >> 5, d = t & 31;
    for (int idx = t; idx < 64; idx += 256) km_s[idx] = KM[(size_t)bh*64 + idx];
    for (int idx = t; idx < 2048; idx += 256) {
        int j = idx >> 5, col = idx & 31;
        kvb[j][col] = (col < 16) ? KVS[(size_t)bh*1024 + j*16 + col]
                                 : KVO[(size_t)bh*1024 + j*16 + (col - 16)];
    }
    __syncthreads();
    bool sim = (d < 16);
    for (int n0 = 0; n0 < NTOK; n0 += 8) {
        int n = n0 + w;
        size_t tokbase = ((size_t)(b*NTOK + n)) * 256;
        float qp = QP[tokbase + h*32 + d];
        float qn = QN[tokbase + h*32 + d];
        qps[w][d] = qp; qns[w][d] = qn;
        __syncwarp();
        float d1 = qp*km_s[d] + qn*km_s[32 + d];
        float d2 = qn*km_s[d] + qp*km_s[32 + d];
#pragma unroll
        for (int off = 16; off; off >>= 1) {
            d1 += __shfl_xor_sync(0xffffffffu, d1, off);
            d2 += __shfl_xor_sync(0xffffffffu, d2, off);
        }
        float acc = 0.f;
#pragma unroll
        for (int j = 0; j < 32; j++) {
            float a = qps[w][j], bb = qns[w][j];
            float m1 = sim ? a : bb;
            float m2 = sim ? bb : a;
            acc += m1*kvb[j][d] + m2*kvb[32 + j][d];
        }
        float den = (sim ? d1 : d2) + 1e-6f;
        float val = acc / den;
        int c = h*32 + d;
        float vdv = VD[(size_t)b*102400 + (size_t)n*256 + c];
        float gg  = G[tokbase + c];
        OUT2[tokbase + c] = (val + vdv) * gg;
        __syncwarp();
    }
}

// ---------------- SE: sigmoid(se_w @ mean_spatial(src)) ----------------
__global__ void k_se(const float* __restrict__ src, const float* __restrict__ sew,
                     float* __restrict__ SE) {
    int b = blockIdx.x, t = threadIdx.x, w = t >> 5, lane = t & 31;
    __shared__ float sm[256];
    for (int ci = 0; ci < 32; ci++) {
        int c = w*32 + ci;
        const float* p = src + (size_t)b*102400 + (size_t)c*400;
        float s = 0.f;
        for (int n = lane; n < 400; n += 32) s += p[n];
#pragma unroll
        for (int off = 16; off; off >>= 1) s += __shfl_xor_sync(0xffffffffu, s, off);
        if (lane == 0) sm[c] = s * (1.0f/400.0f);
    }
    __syncthreads();
    for (int o = t; o < 512; o += 256) {
        const float* wr = sew + (size_t)o*256;
        float acc = 0.f;
        for (int c = 0; c < 256; c++) acc += wr[c] * sm[c];
        SE[(size_t)b*512 + o] = 1.0f / (1.0f + expf(-acc));
    }
}

// ---------------- depthwise 3x3 + GLU(gelu) + SE scale — SMEM tiled ----------------
// grid (cq=4, ystrip=4, b=64); block 256.
// Each block: s1 chans [cq*128, +128), s2 chans [512+cq*128, +128).
// Tile: 7 rows (5 out + 2 halo) x 20 x x 128 ch, for both s1 and s2.
constexpr int DG_CH  = 128;
constexpr int DG_TROW = 20 * DG_CH;                 // floats per row per tensor
constexpr int DG_TILE = 7 * DG_TROW;                // 17920 floats
constexpr int SMEM_DG = (2 * DG_TILE + 2 * DG_CH * 9 + DG_CH) * 4; // ~153KB

__global__ __launch_bounds__(256)
void k_dw_glu(const float* __restrict__ Y, const float* __restrict__ dww,
              const float* __restrict__ SE, float* __restrict__ Y2) {
    extern __shared__ float dsm[];
    float* s1t = dsm;                    // [7][20][128]
    float* s2t = dsm + DG_TILE;          // [7][20][128]
    float* w1  = dsm + 2 * DG_TILE;      // [128][9]
    float* w2  = w1 + DG_CH * 9;         // [128][9]
    float* ses = w2 + DG_CH * 9;         // [128]

    int cq = blockIdx.x, ys = blockIdx.y, b = blockIdx.z;
    int t = threadIdx.x;
    int ch0 = cq * DG_CH;
    int y0 = ys * 5;

    // weights + SE
    for (int i = t; i < DG_CH * 9; i += 256) {
        int ch = i / 9, k = i % 9;
        w1[i] = dww[(ch0 + ch) * 9 + k];
        w2[i] = dww[(512 + ch0 + ch) * 9 + k];
    }
    if (t < DG_CH) ses[t] = SE[(size_t)b * 512 + ch0 + t];

    // load 7 rows (y0-1 .. y0+5), zero-padded
    for (int i = t; i < DG_TILE; i += 256) {
        int r = i / DG_TROW;
        int rem = i - r * DG_TROW;       // x*128 + ch
        int x = rem >> 7, ch = rem & 127;
        int gy = y0 - 1 + r;
        float v1 = 0.f, v2 = 0.f;
        if (gy >= 0 && gy < 20) {
            size_t base = ((size_t)(b * NTOK + gy * 20 + x)) * 1024;
            v1 = Y[base + ch0 + ch];
            v2 = Y[base + 512 + ch0 + ch];
        }
        s1t[i] = v1; s2t[i] = v2;
    }
    __syncthreads();

    // compute 5 rows x 20 x 128
    for (int oi = t; oi < 5 * DG_TROW; oi += 256) {
        int yl = oi / DG_TROW;
        int rem = oi - yl * DG_TROW;
        int x = rem >> 7, ch = rem & 127;
        float s1 = 0.f, s2 = 0.f;
#pragma unroll
        for (int ky = 0; ky < 3; ky++) {
            const float* r1 = s1t + (yl + ky) * DG_TROW + ch;
            const float* r2 = s2t + (yl + ky) * DG_TROW + ch;
            const float* ww1 = w1 + ch * 9 + ky * 3;
            const float* ww2 = w2 + ch * 9 + ky * 3;
#pragma unroll
            for (int kx = 0; kx < 3; kx++) {
                int xx = x + kx - 1;
                if (xx < 0 || xx >= 20) continue;
                s1 += r1[xx * DG_CH] * ww1[kx];
                s2 += r2[xx * DG_CH] * ww2[kx];
            }
        }
        float ge = 0.5f * s1 * (1.0f + erff(s1 * 0.70710678118654752f));
        int y = y0 + yl;
        Y2[((size_t)(b * NTOK + y * 20 + x)) * 512 + ch0 + ch] = ge * s2 * ses[ch];
    }
}

// ---------------- launcher ----------------
extern "C" void kernel_launch(void* const* d_in, const int* in_sizes, int n_in,
                              void* d_out, int out_size) {
    const float* src    = (const float*)d_in[0];
    const float* qg_w   = (const float*)d_in[1];
    const float* qg_b   = (const float*)d_in[2];
    const float* kv_w   = (const float*)d_in[3];
    const float* kv_b   = (const float*)d_in[4];
    const float* proj_w = (const float*)d_in[5];
    const float* proj_b = (const float*)d_in[6];
    const float* dwc_w  = (const float*)d_in[7];
    const float* dwc_b  = (const float*)d_in[8];
    const float* power  = (const float*)d_in[9];
    const float* scale  = (const float*)d_in[10];
    const float* pos    = (const float*)d_in[11];
    const float* pin_w  = (const float*)d_in[12];
    const float* dw_w   = (const float*)d_in[13];
    const float* se_w   = (const float*)d_in[14];
    const float* pout_w = (const float*)d_in[15];
    const float* ln1_w  = (const float*)d_in[16];
    const float* ln1_b  = (const float*)d_in[17];
    const float* ln2_w  = (const float*)d_in[18];
    const float* ln2_b  = (const float*)d_in[19];
    float* out = (float*)d_out;

    float* scr = nullptr;
    cudaGetSymbolAddress((void**)&scr, d_scratch);

    float* XT   = scr + O_XT;
    float* G    = scr + O_G;
    float* QP   = scr + O_QP;
    float* QN   = scr + O_QN;
    float* KP   = scr + O_KP;
    float* KN   = scr + O_KN;
    float* V    = scr + O_V;
    float* VD   = scr + O_VD;
    float* KM   = scr + O_KM;
    float* KVS  = scr + O_KVS;
    float* KVO  = scr + O_KVO;
    float* OUT2 = scr + O_OUT2;
    float* S    = scr + O_S;
    float* Y    = scr + O_Y;
    float* Y2   = scr + O_Y2;
    float* TMP  = scr + O_TMP;
    float* SE   = scr + O_SE;
    float* INV  = scr + O_INV;
    float* PW   = scr + O_PW;

    static bool attr_set = false;
    if (!attr_set) {
        cudaFuncSetAttribute(gemm_mma<1,1>, cudaFuncAttributeMaxDynamicSharedMemorySize, SMEM_GEMM);
        cudaFuncSetAttribute(gemm_mma<1,2>, cudaFuncAttributeMaxDynamicSharedMemorySize, SMEM_GEMM);
        cudaFuncSetAttribute(gemm_mma<1,0>, cudaFuncAttributeMaxDynamicSharedMemorySize, SMEM_GEMM);
        cudaFuncSetAttribute(gemm_ln<256>, cudaFuncAttributeMaxDynamicSharedMemorySize, SMEM_GLN);
        cudaFuncSetAttribute(gemm_ln<512>, cudaFuncAttributeMaxDynamicSharedMemorySize, SMEM_GLN);
        cudaFuncSetAttribute(k_dw_glu, cudaFuncAttributeMaxDynamicSharedMemorySize, SMEM_DG);
        attr_set = true;
    }

    // 1. params
    k_prep<<<1, 256>>>(scale, power, INV, PW);
    // 2. src -> token-major
    k_tr_src<<<dim3(13, 8, BATCH), dim3(32, 32)>>>(src, XT);
    // 3. qg GEMM + fused pow/gate epilogue
    gemm_mma<1,1><<<dim3(4, 200), 256, SMEM_GEMM>>>(XT, qg_w, qg_b, nullptr,
        TOKS, 512, 256, INV, PW, nullptr, QP, QN, G);
    // 4. kv GEMM + fused pos/pow/V epilogue
    gemm_mma<1,2><<<dim3(4, 200), 256, SMEM_GEMM>>>(XT, kv_w, kv_b, nullptr,
        TOKS, 512, 256, INV, PW, pos, KP, KN, V);
    // 5. per-(b,h) reductions
    k_reduce<<<512, 256>>>(KP, KN, V, KM, KVS, KVO);
    // 6. depthwise 5x5 on reinterpreted v
    k_dwc<<<1024, 256>>>(V, dwc_w, dwc_b, VD);
    // 7. attention output + vd + gate
    k_attn_out<<<512, 256>>>(QP, QN, KM, KVS, KVO, VD, G, OUT2);
    // 8. proj + residual + LN1 fused
    gemm_ln<256><<<200, 512, SMEM_GLN>>>(OUT2, proj_w, proj_b, XT, ln1_w, ln1_b, S);
    // 9. SE gate from raw src
    k_se<<<BATCH, 256>>>(src, se_w, SE);
    // 10. pin 1x1
    gemm_mma<1,0><<<dim3(8, 200), 256, SMEM_GEMM>>>(S, pin_w, nullptr, Y,
        TOKS, 1024, 256, nullptr, nullptr, nullptr, nullptr, nullptr, nullptr);
    // 11. dw 3x3 + glu + se (smem tiled)
    k_dw_glu<<<dim3(4, 4, BATCH), 256, SMEM_DG>>>(Y, dw_w, SE, Y2);
    // 12. pout + residual + LN2 fused
    gemm_ln<512><<<200, 512, SMEM_GLN>>>(Y2, pout_w, nullptr, S, ln2_w, ln2_b, TMP);
    // 13. transpose to NCHW output
    k_tr_out<<<dim3(13, 8, BATCH), dim3(32, 32)>>>(TMP, out);
}

// round 6
// speedup vs baseline: 1.8568x; 1.0752x over previous
#include <cuda_runtime.h>
#include <cuda_bf16.h>
#include <math.h>
#include <stdint.h>

// ---------------- problem constants ----------------
#define BATCH 64
#define CCH   256
#define NTOK  400
#define TOKS  (BATCH*NTOK) // 25600

// ---------------- scratch layout (float units) ----------------
constexpr size_t O_XT    = 0;
constexpr size_t O_G     = O_XT    + (size_t)TOKS*256;
constexpr size_t O_QP    = O_G     + (size_t)TOKS*256;
constexpr size_t O_QN    = O_QP    + (size_t)TOKS*256;
constexpr size_t O_KP    = O_QN    + (size_t)TOKS*256;
constexpr size_t O_KN    = O_KP    + (size_t)TOKS*256;
constexpr size_t O_V     = O_KN    + (size_t)TOKS*256;
constexpr size_t O_VD    = O_V     + (size_t)TOKS*256;
constexpr size_t O_KM    = O_VD    + (size_t)TOKS*256;
constexpr size_t O_KVS   = O_KM    + (size_t)512*64;
constexpr size_t O_KVO   = O_KVS   + (size_t)512*1024;
constexpr size_t O_OUT2H = O_KVO   + (size_t)512*1024;   // bf16 TOKS*256
constexpr size_t O_S     = O_OUT2H + (size_t)TOKS*128;
constexpr size_t O_SH    = O_S     + (size_t)TOKS*256;   // bf16 TOKS*256
constexpr size_t O_Y     = O_SH    + (size_t)TOKS*128;
constexpr size_t O_Y2H   = O_Y     + (size_t)TOKS*1024;  // bf16 TOKS*512
constexpr size_t O_TMP   = O_Y2H   + (size_t)TOKS*256;
constexpr size_t O_SE    = O_TMP   + (size_t)TOKS*256;
constexpr size_t O_INV   = O_SE    + (size_t)BATCH*512;
constexpr size_t O_PW    = O_INV   + 256;
constexpr size_t O_WPJH  = O_PW    + 256;                // bf16 256*256
constexpr size_t O_WPIH  = O_WPJH  + 32768;              // bf16 1024*256
constexpr size_t O_WPOH  = O_WPIH  + 131072;             // bf16 256*512
constexpr size_t SCR_TOTAL = O_WPOH + 65536;

__device__ __align__(256) float d_scratch[SCR_TOTAL];

// =======================================================================
// helpers
// =======================================================================
__device__ __forceinline__ uint32_t smem_u32(const void* p) {
    uint32_t a;
    asm("{ .reg .u64 t; cvta.to.shared.u64 t, %1; cvt.u32.u64 %0, t; }" : "=r"(a) : "l"(p));
    return a;
}
__device__ __forceinline__ uint32_t f2tf32(float x) {
    uint32_t u; asm("cvt.rna.tf32.f32 %0, %1;" : "=r"(u) : "f"(x)); return u;
}
__device__ __forceinline__ void cp16(uint32_t s, const void* g) {
    asm volatile("cp.async.ca.shared.global [%0], [%1], 16;" :: "r"(s), "l"(g));
}
#define CP_COMMIT() asm volatile("cp.async.commit_group;" ::: "memory")
#define CP_WAIT(n)  asm volatile("cp.async.wait_group %0;" :: "n"(n) : "memory")

__device__ __forceinline__ void mma_tf32(float* d, const uint32_t* a, const uint32_t* b) {
    asm volatile(
        "mma.sync.aligned.m16n8k8.row.col.f32.tf32.tf32.f32 "
        "{%0,%1,%2,%3}, {%4,%5,%6,%7}, {%8,%9}, {%0,%1,%2,%3};"
        : "+f"(d[0]), "+f"(d[1]), "+f"(d[2]), "+f"(d[3])
        : "r"(a[0]), "r"(a[1]), "r"(a[2]), "r"(a[3]), "r"(b[0]), "r"(b[1]));
}
__device__ __forceinline__ void mma_bf16(float* d, const uint32_t* a, const uint32_t* b) {
    asm volatile(
        "mma.sync.aligned.m16n8k16.row.col.f32.bf16.bf16.f32 "
        "{%0,%1,%2,%3}, {%4,%5,%6,%7}, {%8,%9}, {%0,%1,%2,%3};"
        : "+f"(d[0]), "+f"(d[1]), "+f"(d[2]), "+f"(d[3])
        : "r"(a[0]), "r"(a[1]), "r"(a[2]), "r"(a[3]), "r"(b[0]), "r"(b[1]));
}

// =======================================================================
// gemm_qgkv: merged qg + kv GEMMs (tf32). grid (4, 200, 2).
// z=0: qg -> QP/QN (pow), G.  z=1: kv -> KP/KN (pow, +pos), V.
// M=TOKS, N=512, K=256. CTA tile 128x128.
// =======================================================================
constexpr int GS_ROW   = 36;
constexpr int GS_TILE  = 128 * GS_ROW;
constexpr int GS_BUF   = 2 * GS_TILE;
constexpr int SMEM_GEMM = 2 * GS_BUF * 4;     // 73728

__global__ __launch_bounds__(256, 2)
void gemm_qgkv(const float* __restrict__ A,
               const float* __restrict__ wq, const float* __restrict__ bq,
               const float* __restrict__ wk, const float* __restrict__ bk,
               const float* __restrict__ pos,
               const float* __restrict__ invsc, const float* __restrict__ pw,
               float* __restrict__ QP, float* __restrict__ QN, float* __restrict__ G,
               float* __restrict__ KP, float* __restrict__ KN, float* __restrict__ V) {
    const int K = 256;
    extern __shared__ float sm[];
    const uint32_t sbase = smem_u32(sm);
    const int t = threadIdx.x, lane = t & 31, wid = t >> 5;
    const int wm = (wid >> 2) * 64;
    const int wn = (wid & 3) * 32;
    const int bm = blockIdx.y * 128, bn = blockIdx.x * 128;
    const int g4 = lane >> 2, l4 = lane & 3;
    const bool isKV = (blockIdx.z != 0);
    const float* Bw  = isKV ? wk : wq;
    const float* bias = isKV ? bk : bq;
    float* P1 = isKV ? KP : QP;
    float* P2 = isKV ? KN : QN;
    float* P3 = isKV ? V  : G;

    auto load_chunk = [&](int ch, int buf) {
        int k0 = ch << 5;
        uint32_t sb = sbase + (uint32_t)buf * (GS_BUF * 4);
#pragma unroll
        for (int i = 0; i < 8; i++) {
            int o = t + i * 256;
            int isB = o >> 10;
            int row = (o & 1023) >> 3;
            int seg = o & 7;
            const float* g = (isB ? Bw + (size_t)(bn + row) * K
                                  : A  + (size_t)(bm + row) * K) + k0 + seg * 4;
            uint32_t s = sb + (uint32_t)(isB * (GS_TILE * 4) + row * (GS_ROW * 4) + seg * 16);
            cp16(s, g);
        }
        CP_COMMIT();
    };

    float acc[4][4][4];
#pragma unroll
    for (int mi = 0; mi < 4; mi++)
#pragma unroll
        for (int ni = 0; ni < 4; ni++)
#pragma unroll
            for (int k = 0; k < 4; k++) acc[mi][ni][k] = 0.0f;

    load_chunk(0, 0);
    load_chunk(1, 1);
    const int NC = 8;
    for (int ch = 0; ch < NC; ch++) {
        if (ch + 1 < NC) { CP_WAIT(1); } else { CP_WAIT(0); }
        __syncthreads();
        const float* Ab = sm + (ch & 1) * GS_BUF;
        const float* Bb = Ab + GS_TILE;
#pragma unroll
        for (int s = 0; s < 4; s++) {
            int c0 = s * 8 + l4;
            uint32_t ah[4][4], bh[4][2];
#pragma unroll
            for (int mi = 0; mi < 4; mi++) {
                const float* ap = Ab + (wm + mi * 16 + g4) * GS_ROW;
                ah[mi][0] = f2tf32(ap[c0]);
                ah[mi][1] = f2tf32(ap[8 * GS_ROW + c0]);
                ah[mi][2] = f2tf32(ap[c0 + 4]);
                ah[mi][3] = f2tf32(ap[8 * GS_ROW + c0 + 4]);
            }
#pragma unroll
            for (int ni = 0; ni < 4; ni++) {
                const float* bp = Bb + (wn + ni * 8 + g4) * GS_ROW;
                bh[ni][0] = f2tf32(bp[c0]);
                bh[ni][1] = f2tf32(bp[c0 + 4]);
            }
#pragma unroll
            for (int mi = 0; mi < 4; mi++)
#pragma unroll
                for (int ni = 0; ni < 4; ni++)
                    mma_tf32(acc[mi][ni], ah[mi], bh[ni]);
        }
        __syncthreads();
        if (ch + 2 < NC) load_chunk(ch + 2, ch & 1);
    }

    bool first_half = (bn < 256);
#pragma unroll
    for (int mi = 0; mi < 4; mi++) {
#pragma unroll
        for (int half = 0; half < 2; half++) {
            int r = bm + wm + mi * 16 + g4 + half * 8;
            int tok = r % NTOK;
#pragma unroll
            for (int ni = 0; ni < 4; ni++) {
#pragma unroll
                for (int j = 0; j < 2; j++) {
                    int ccol = bn + wn + ni * 8 + 2 * l4 + j;
                    float v = acc[mi][ni][half * 2 + j] + bias[ccol];
                    if (first_half) {
                        float x = isKV ? (v + pos[(size_t)tok * 256 + ccol]) * invsc[ccol]
                                       : v * invsc[ccol];
                        float p = pw[ccol];
                        float xp = 0.f, xn = 0.f;
                        if (x > 0.f)      xp = __powf(fmaxf(x, 1e-30f), p);
                        else if (x < 0.f) xn = __powf(fmaxf(-x, 1e-30f), p);
                        P1[(size_t)r * 256 + ccol] = xp;
                        P2[(size_t)r * 256 + ccol] = xn;
                    } else {
                        P3[(size_t)r * 256 + (ccol - 256)] = v;
                    }
                }
            }
        }
    }
}

// =======================================================================
// gemm_bf: bf16 GEMM, C fp32 = A@B^T. 128x128 tile, K-chunk 64, 256 thr.
// A: MxK bf16, B: NxK bf16. Used for pin (N=1024, K=256, bias none).
// =======================================================================
constexpr int HROWB = 144;                 // bytes per smem row (64 bf16 + pad)
constexpr int HROWW = 36;                  // words per row
constexpr int HB_TILE_B = 128 * HROWB;     // 18432 bytes
constexpr int HB_BUF_B  = 2 * HB_TILE_B;   // 36864
constexpr int SMEM_GBF  = 2 * HB_BUF_B;    // 73728

__global__ __launch_bounds__(256, 2)
void gemm_bf(const __nv_bfloat16* __restrict__ A, const __nv_bfloat16* __restrict__ Bw,
             float* __restrict__ C, int M, int N, int K) {
    extern __shared__ float sm[];
    const uint32_t sbase = smem_u32(sm);
    char* cbase = (char*)sm;
    const int t = threadIdx.x, lane = t & 31, wid = t >> 5;
    const int wm = (wid >> 2) * 64;
    const int wn = (wid & 3) * 32;
    const int bm = blockIdx.y * 128, bn = blockIdx.x * 128;
    const int g4 = lane >> 2, l4 = lane & 3;
    const int NC = K >> 6;

    auto load_chunk = [&](int ch, int buf) {
        int k0 = ch << 6;
        uint32_t sb = sbase + (uint32_t)buf * HB_BUF_B;
#pragma unroll
        for (int i = 0; i < 8; i++) {
            int o = t + i * 256;
            int isB = o >> 10;
            int row = (o & 1023) >> 3;
            int seg = o & 7;
            const __nv_bfloat16* g = (isB ? Bw + (size_t)(bn + row) * K
                                          : A  + (size_t)(bm + row) * K) + k0 + seg * 8;
            uint32_t s = sb + (uint32_t)(isB * HB_TILE_B + row * HROWB + seg * 16);
            cp16(s, g);
        }
        CP_COMMIT();
    };

    float acc[4][4][4];
#pragma unroll
    for (int mi = 0; mi < 4; mi++)
#pragma unroll
        for (int ni = 0; ni < 4; ni++)
#pragma unroll
            for (int k = 0; k < 4; k++) acc[mi][ni][k] = 0.0f;

    load_chunk(0, 0);
    if (NC > 1) load_chunk(1, 1);

    for (int ch = 0; ch < NC; ch++) {
        if (ch + 1 < NC) { CP_WAIT(1); } else { CP_WAIT(0); }
        __syncthreads();
        const uint32_t* Ab = (const uint32_t*)(cbase + (ch & 1) * HB_BUF_B);
        const uint32_t* Bb = (const uint32_t*)(cbase + (ch & 1) * HB_BUF_B + HB_TILE_B);
#pragma unroll
        for (int s = 0; s < 4; s++) {
            int c0 = s * 8 + l4;
            uint32_t ah[4][4], bh[4][2];
#pragma unroll
            for (int mi = 0; mi < 4; mi++) {
                int r0 = wm + mi * 16 + g4;
                ah[mi][0] = Ab[r0 * HROWW + c0];
                ah[mi][1] = Ab[(r0 + 8) * HROWW + c0];
                ah[mi][2] = Ab[r0 * HROWW + c0 + 4];
                ah[mi][3] = Ab[(r0 + 8) * HROWW + c0 + 4];
            }
#pragma unroll
            for (int ni = 0; ni < 4; ni++) {
                int n0 = wn + ni * 8 + g4;
                bh[ni][0] = Bb[n0 * HROWW + c0];
                bh[ni][1] = Bb[n0 * HROWW + c0 + 4];
            }
#pragma unroll
            for (int mi = 0; mi < 4; mi++)
#pragma unroll
                for (int ni = 0; ni < 4; ni++)
                    mma_bf16(acc[mi][ni], ah[mi], bh[ni]);
        }
        __syncthreads();
        if (ch + 2 < NC) load_chunk(ch + 2, ch & 1);
    }

#pragma unroll
    for (int mi = 0; mi < 4; mi++) {
        int r0 = bm + wm + mi * 16 + g4;
#pragma unroll
        for (int ni = 0; ni < 4; ni++) {
            int cb = bn + wn + ni * 8 + 2 * l4;
            *(float2*)&C[(size_t)r0 * N + cb]       = make_float2(acc[mi][ni][0], acc[mi][ni][1]);
            *(float2*)&C[(size_t)(r0 + 8) * N + cb] = make_float2(acc[mi][ni][2], acc[mi][ni][3]);
        }
    }
}

// =======================================================================
// gemm_bf_ln: OUT = LN( RES + A@Bw^T (+bias) ), N=256, bf16 inputs, 512 thr.
// WH: also write bf16 copy of OUT.
// =======================================================================
constexpr int HL_TA_B  = 128 * HROWB;          // A tile bytes
constexpr int HL_BUF_B = (128 + 256) * HROWB;  // 55296
constexpr int SMEM_GBLN = 2 * HL_BUF_B;        // 110592

template<int KD, bool WH>
__global__ __launch_bounds__(512)
void gemm_bf_ln(const __nv_bfloat16* __restrict__ A, const __nv_bfloat16* __restrict__ Bw,
                const float* __restrict__ bias, const float* __restrict__ RES,
                const float* __restrict__ lw, const float* __restrict__ lb,
                float* __restrict__ OUT, __nv_bfloat16* __restrict__ OUTH) {
    const int N = 256;
    extern __shared__ float sm[];
    const uint32_t sbase = smem_u32(sm);
    char* cbase = (char*)sm;
    const int t = threadIdx.x, lane = t & 31, wid = t >> 5;
    const int wm = (wid >> 2) * 32;
    const int wn = (wid & 3) * 64;
    const int bm = blockIdx.x * 128;
    const int g4 = lane >> 2, l4 = lane & 3;
    const int NC = KD >> 6;

    auto load_chunk = [&](int ch, int buf) {
        int k0 = ch << 6;
        uint32_t sb = sbase + (uint32_t)buf * HL_BUF_B;
#pragma unroll
        for (int i = 0; i < 6; i++) {
            int o = t + i * 512;
            bool isB = o >= 1024;
            int row = isB ? ((o - 1024) >> 3) : (o >> 3);
            int seg = o & 7;
            const __nv_bfloat16* g = (isB ? Bw + (size_t)row * KD
                                          : A  + (size_t)(bm + row) * KD) + k0 + seg * 8;
            uint32_t s = sb + (uint32_t)((isB ? HL_TA_B : 0) + row * HROWB + seg * 16);
            cp16(s, g);
        }
        CP_COMMIT();
    };

    float acc[2][8][4];
#pragma unroll
    for (int mi = 0; mi < 2; mi++)
#pragma unroll
        for (int ni = 0; ni < 8; ni++)
#pragma unroll
            for (int k = 0; k < 4; k++) acc[mi][ni][k] = 0.0f;

    load_chunk(0, 0);
    if (NC > 1) load_chunk(1, 1);

    for (int ch = 0; ch < NC; ch++) {
        if (ch + 1 < NC) { CP_WAIT(1); } else { CP_WAIT(0); }
        __syncthreads();
        const uint32_t* Ab = (const uint32_t*)(cbase + (ch & 1) * HL_BUF_B);
        const uint32_t* Bb = (const uint32_t*)(cbase + (ch & 1) * HL_BUF_B + HL_TA_B);
#pragma unroll
        for (int s = 0; s < 4; s++) {
            int c0 = s * 8 + l4;
            uint32_t af[2][4], bf[8][2];
#pragma unroll
            for (int mi = 0; mi < 2; mi++) {
                int r0 = wm + mi * 16 + g4;
                af[mi][0] = Ab[r0 * HROWW + c0];
                af[mi][1] = Ab[(r0 + 8) * HROWW + c0];
                af[mi][2] = Ab[r0 * HROWW + c0 + 4];
                af[mi][3] = Ab[(r0 + 8) * HROWW + c0 + 4];
            }
#pragma unroll
            for (int ni = 0; ni < 8; ni++) {
                int n0 = wn + ni * 8 + g4;
                bf[ni][0] = Bb[n0 * HROWW + c0];
                bf[ni][1] = Bb[n0 * HROWW + c0 + 4];
            }
#pragma unroll
            for (int mi = 0; mi < 2; mi++)
#pragma unroll
                for (int ni = 0; ni < 8; ni++)
                    mma_bf16(acc[mi][ni], af[mi], bf[ni]);
        }
        __syncthreads();
        if (ch + 2 < NC) load_chunk(ch + 2, ch & 1);
    }

    __syncthreads();
    float* ssum = sm;
    float* ssq  = sm + 512;

#pragma unroll
    for (int mi = 0; mi < 2; mi++)
#pragma unroll
        for (int half = 0; half < 2; half++) {
            int r = bm + wm + mi * 16 + g4 + half * 8;
#pragma unroll
            for (int ni = 0; ni < 8; ni++)
#pragma unroll
                for (int j = 0; j < 2; j++) {
                    int c = wn + ni * 8 + 2 * l4 + j;
                    float b = bias ? bias[c] : 0.f;
                    acc[mi][ni][half * 2 + j] += b + RES[(size_t)r * N + c];
                }
        }
#pragma unroll
    for (int mi = 0; mi < 2; mi++)
#pragma unroll
        for (int half = 0; half < 2; half++) {
            float s = 0.f, q = 0.f;
#pragma unroll
            for (int ni = 0; ni < 8; ni++)
#pragma unroll
                for (int j = 0; j < 2; j++) {
                    float v = acc[mi][ni][half * 2 + j];
                    s += v; q += v * v;
                }
            s += __shfl_xor_sync(0xffffffffu, s, 1);
            s += __shfl_xor_sync(0xffffffffu, s, 2);
            q += __shfl_xor_sync(0xffffffffu, q, 1);
            q += __shfl_xor_sync(0xffffffffu, q, 2);
            if (l4 == 0) {
                int lr = wm + mi * 16 + g4 + half * 8;
                ssum[(wid & 3) * 128 + lr] = s;
                ssq[(wid & 3) * 128 + lr]  = q;
            }
        }
    __syncthreads();
#pragma unroll
    for (int mi = 0; mi < 2; mi++)
#pragma unroll
        for (int half = 0; half < 2; half++) {
            int lr = wm + mi * 16 + g4 + half * 8;
            float s = ssum[lr] + ssum[128 + lr] + ssum[256 + lr] + ssum[384 + lr];
            float q = ssq[lr]  + ssq[128 + lr]  + ssq[256 + lr]  + ssq[384 + lr];
            float mean = s * (1.0f / 256.0f);
            float var  = q * (1.0f / 256.0f) - mean * mean;
            float inv  = rsqrtf(var + 1e-6f);
            int r = bm + lr;
#pragma unroll
            for (int ni = 0; ni < 8; ni++)
#pragma unroll
                for (int j = 0; j < 2; j++) {
                    int c = wn + ni * 8 + 2 * l4 + j;
                    float v = acc[mi][ni][half * 2 + j];
                    float o = lw[c] * (v - mean) * inv + lb[c];
                    OUT[(size_t)r * N + c] = o;
                    if (WH) OUTH[(size_t)r * N + c] = __float2bfloat16(o);
                }
        }
}

// ---------------- param prep ----------------
__global__ void k_prep(const float* __restrict__ scale, const float* __restrict__ power,
                       float* __restrict__ invsc, float* __restrict__ pw) {
    int c = threadIdx.x;
    float sp = log1pf(expf(scale[c]));
    invsc[c] = 1.0f / sp;
    pw[c] = 1.0f + 4.0f / (1.0f + expf(-power[c]));
}

// ---------------- weight -> bf16 convert ----------------
__global__ void k_cvtw(const float* __restrict__ p1, __nv_bfloat16* __restrict__ o1, int n1,
                       const float* __restrict__ p2, __nv_bfloat16* __restrict__ o2, int n2,
                       const float* __restrict__ p3, __nv_bfloat16* __restrict__ o3, int n3) {
    int total = n1 + n2 + n3;
    for (int i = blockIdx.x * blockDim.x + threadIdx.x; i < total; i += gridDim.x * blockDim.x) {
        if (i < n1) o1[i] = __float2bfloat16(p1[i]);
        else if (i < n1 + n2) o2[i - n1] = __float2bfloat16(p2[i - n1]);
        else o3[i - n1 - n2] = __float2bfloat16(p3[i - n1 - n2]);
    }
}

// ---------------- transpose (B,C,400) -> (B,400,C) ----------------
__global__ void k_tr_src(const float* __restrict__ src, float* __restrict__ XT) {
    __shared__ float tile[32][33];
    int b = blockIdx.z, cb = blockIdx.y * 32, nb = blockIdx.x * 32;
    int tx = threadIdx.x, ty = threadIdx.y;
    int n = nb + tx, c = cb + ty;
    if (n < NTOK) tile[ty][tx] = src[(size_t)b*CCH*NTOK + (size_t)c*NTOK + n];
    __syncthreads();
    n = nb + ty; c = cb + tx;
    if (n < NTOK) XT[((size_t)b*NTOK + n)*CCH + c] = tile[tx][ty];
}

// ---------------- transpose (B,400,C) -> (B,C,400) ----------------
__global__ void k_tr_out(const float* __restrict__ TMP, float* __restrict__ OUT) {
    __shared__ float tile[32][33];
    int b = blockIdx.z, cb = blockIdx.y * 32, nb = blockIdx.x * 32;
    int tx = threadIdx.x, ty = threadIdx.y;
    int n = nb + ty, c = cb + tx;
    if (n < NTOK) tile[ty][tx] = TMP[((size_t)b*NTOK + n)*CCH + c];
    __syncthreads();
    c = cb + ty; n = nb + tx;
    if (n < NTOK) OUT[(size_t)b*CCH*NTOK + (size_t)c*NTOK + n] = tile[tx][ty];
}

// =======================================================================
// k_fused: blocks [0,512) -> per-(b,h) reductions
//          blocks [512,1536) -> depthwise 5x5 on v
//          blocks [1536,1600) -> SE gate
// =======================================================================
__global__ __launch_bounds__(256)
void k_fused(const float* __restrict__ KP, const float* __restrict__ KN,
             const float* __restrict__ V,
             float* __restrict__ KM, float* __restrict__ KVS, float* __restrict__ KVO,
             const float* __restrict__ dwcw, const float* __restrict__ dwcb,
             float* __restrict__ VD,
             const float* __restrict__ src, const float* __restrict__ sew,
             float* __restrict__ SE) {
    __shared__ float fsm[14*640 + 800 + 32];
    int bid = blockIdx.x;
    int t = threadIdx.x;

    if (bid < 512) {
        // ---- reduce ----
        float* kc_s = fsm;            // [16][64]
        float* v_s  = fsm + 1024;     // [16][32]
        int bh = bid, b = bh >> 3, h = bh & 7;
        int j = t >> 2, e0 = (t & 3) << 2;
        float accs[4] = {0,0,0,0}, acco[4] = {0,0,0,0}, accm = 0.f;
        for (int n0 = 0; n0 < NTOK; n0 += 16) {
            for (int idx = t; idx < 16*64; idx += 256) {
                int nl = idx >> 6, jj = idx & 63;
                size_t base = ((size_t)(b*NTOK + n0 + nl))*256 + h*32 + (jj & 31);
                kc_s[idx] = (jj < 32) ? KP[base] : KN[base];
            }
            for (int idx = t; idx < 16*32; idx += 256) {
                int nl = idx >> 5, ee = idx & 31;
                size_t base = ((size_t)(b*NTOK + n0 + nl))*256 + (ee < 16 ? h*16 + ee : 128 + h*16 + ee - 16);
                v_s[idx] = V[base];
            }
            __syncthreads();
#pragma unroll
            for (int nl = 0; nl < 16; nl++) {
                float kcv = kc_s[nl*64 + j];
                accm += kcv;
#pragma unroll
                for (int q = 0; q < 4; q++) {
                    accs[q] += kcv * v_s[nl*32 + e0 + q];
                    acco[q] += kcv * v_s[nl*32 + 16 + e0 + q];
                }
            }
            __syncthreads();
        }
        const float invN = 1.0f / (float)NTOK;
        size_t ob = (size_t)bh*1024 + (size_t)j*16 + e0;
#pragma unroll
        for (int q = 0; q < 4; q++) { KVS[ob+q] = accs[q]*invN; KVO[ob+q] = acco[q]*invN; }
        if ((t & 3) == 0) KM[(size_t)bh*64 + j] = accm * invN;
    } else if (bid < 1536) {
        // ---- dwc 5x5 ----
        float* tile = fsm;
        float* ws   = fsm + 14*640;
        float* bs   = ws + 800;
        int blk = bid - 512;
        int half = blk & 1, g = (blk >> 1) & 7, b = blk >> 4;
        for (int i = t; i < 800; i += 256) ws[i] = dwcw[i];
        if (t < 32) bs[t] = dwcb[t];
        const float* Vb = V + (size_t)b*102400 + (size_t)g*12800;
        int r0 = half*10 - 2;
        for (int i = t; i < 14*640; i += 256) {
            int rr = i / 640, rem = i - rr*640;
            int r = r0 + rr;
            tile[i] = (r >= 0 && r < 20) ? Vb[r*640 + rem] : 0.0f;
        }
        __syncthreads();
        for (int oi = t; oi < 10*640; oi += 256) {
            int yl = oi / 640, rem = oi - yl*640;
            int x = rem >> 5, dd = rem & 31;
            int lrow = yl + 2;
            float acc = bs[dd];
#pragma unroll
            for (int ky = 0; ky < 5; ky++) {
#pragma unroll
                for (int kx = 0; kx < 5; kx++) {
                    int xx = x + kx - 2;
                    if (xx >= 0 && xx < 20)
                        acc += tile[(lrow + ky - 2)*640 + xx*32 + dd] * ws[dd*25 + ky*5 + kx];
                }
            }
            int y = half*10 + yl;
            VD[(size_t)b*102400 + (size_t)g*12800 + (size_t)y*640 + rem] = acc;
        }
    } else {
        // ---- SE ----
        float* smv = fsm;
        int b = bid - 1536;
        int w = t >> 5, lane = t & 31;
        for (int ci = 0; ci < 32; ci++) {
            int c = w*32 + ci;
            const float* p = src + (size_t)b*102400 + (size_t)c*400;
            float s = 0.f;
            for (int n = lane; n < 400; n += 32) s += p[n];
#pragma unroll
            for (int off = 16; off; off >>= 1) s += __shfl_xor_sync(0xffffffffu, s, off);
            if (lane == 0) smv[c] = s * (1.0f/400.0f);
        }
        __syncthreads();
        for (int o = t; o < 512; o += 256) {
            const float* wr = sew + (size_t)o*256;
            float acc = 0.f;
            for (int c = 0; c < 256; c++) acc += wr[c] * smv[c];
            SE[(size_t)b*512 + o] = 1.0f / (1.0f + expf(-acc));
        }
    }
}

// ---------------- attention output + vd + gate (bf16 out) ----------------
__global__ __launch_bounds__(256)
void k_attn_out(const float* __restrict__ QP, const float* __restrict__ QN,
                const float* __restrict__ KM, const float* __restrict__ KVS,
                const float* __restrict__ KVO, const float* __restrict__ VD,
                const float* __restrict__ G, __nv_bfloat16* __restrict__ OUT2H) {
    int bh = blockIdx.x, b = bh >> 3, h = bh & 7;
    __shared__ float km_s[64];
    __shared__ float kvb[64][32];
    __shared__ float qps[8][32], qns[8][32];
    int t = threadIdx.x, w = t >> 5, d = t & 31;
    for (int idx = t; idx < 64; idx += 256) km_s[idx] = KM[(size_t)bh*64 + idx];
    for (int idx = t; idx < 2048; idx += 256) {
        int j = idx >> 5, col = idx & 31;
        kvb[j][col] = (col < 16) ? KVS[(size_t)bh*1024 + j*16 + col]
                                 : KVO[(size_t)bh*1024 + j*16 + (col - 16)];
    }
    __syncthreads();
    bool sim = (d < 16);
    for (int n0 = 0; n0 < NTOK; n0 += 8) {
        int n = n0 + w;
        size_t tokbase = ((size_t)(b*NTOK + n)) * 256;
        float qp = QP[tokbase + h*32 + d];
        float qn = QN[tokbase + h*32 + d];
        qps[w][d] = qp; qns[w][d] = qn;
        __syncwarp();
        float d1 = qp*km_s[d] + qn*km_s[32 + d];
        float d2 = qn*km_s[d] + qp*km_s[32 + d];
#pragma unroll
        for (int off = 16; off; off >>= 1) {
            d1 += __shfl_xor_sync(0xffffffffu, d1, off);
            d2 += __shfl_xor_sync(0xffffffffu, d2, off);
        }
        float acc = 0.f;
#pragma unroll
        for (int j = 0; j < 32; j++) {
            float a = qps[w][j], bb = qns[w][j];
            float m1 = sim ? a : bb;
            float m2 = sim ? bb : a;
            acc += m1*kvb[j][d] + m2*kvb[32 + j][d];
        }
        float den = (sim ? d1 : d2) + 1e-6f;
        float val = acc / den;
        int c = h*32 + d;
        float vdv = VD[(size_t)b*102400 + (size_t)n*256 + c];
        float gg  = G[tokbase + c];
        OUT2H[tokbase + c] = __float2bfloat16((val + vdv) * gg);
        __syncwarp();
    }
}

// ---------------- dw3x3 + GLU(gelu) + SE scale — SMEM tiled, bf16 out ----------------
constexpr int DG_CH  = 128;
constexpr int DG_TROW = 20 * DG_CH;
constexpr int DG_TILE = 7 * DG_TROW;
constexpr int SMEM_DG = (2 * DG_TILE + 2 * DG_CH * 9 + DG_CH) * 4;

__global__ __launch_bounds__(256)
void k_dw_glu(const float* __restrict__ Y, const float* __restrict__ dww,
              const float* __restrict__ SE, __nv_bfloat16* __restrict__ Y2H) {
    extern __shared__ float dsm[];
    float* s1t = dsm;
    float* s2t = dsm + DG_TILE;
    float* w1  = dsm + 2 * DG_TILE;
    float* w2  = w1 + DG_CH * 9;
    float* ses = w2 + DG_CH * 9;

    int cq = blockIdx.x, ys = blockIdx.y, b = blockIdx.z;
    int t = threadIdx.x;
    int ch0 = cq * DG_CH;
    int y0 = ys * 5;

    for (int i = t; i < DG_CH * 9; i += 256) {
        int ch = i / 9, k = i % 9;
        w1[i] = dww[(ch0 + ch) * 9 + k];
        w2[i] = dww[(512 + ch0 + ch) * 9 + k];
    }
    if (t < DG_CH) ses[t] = SE[(size_t)b * 512 + ch0 + t];

    for (int i = t; i < DG_TILE; i += 256) {
        int r = i / DG_TROW;
        int rem = i - r * DG_TROW;
        int x = rem >> 7, ch = rem & 127;
        int gy = y0 - 1 + r;
        float v1 = 0.f, v2 = 0.f;
        if (gy >= 0 && gy < 20) {
            size_t base = ((size_t)(b * NTOK + gy * 20 + x)) * 1024;
            v1 = Y[base + ch0 + ch];
            v2 = Y[base + 512 + ch0 + ch];
        }
        s1t[i] = v1; s2t[i] = v2;
    }
    __syncthreads();

    for (int oi = t; oi < 5 * DG_TROW; oi += 256) {
        int yl = oi / DG_TROW;
        int rem = oi - yl * DG_TROW;
        int x = rem >> 7, ch = rem & 127;
        float s1 = 0.f, s2 = 0.f;
#pragma unroll
        for (int ky = 0; ky < 3; ky++) {
            const float* r1 = s1t + (yl + ky) * DG_TROW + ch;
            const float* r2 = s2t + (yl + ky) * DG_TROW + ch;
            const float* ww1 = w1 + ch * 9 + ky * 3;
            const float* ww2 = w2 + ch * 9 + ky * 3;
#pragma unroll
            for (int kx = 0; kx < 3; kx++) {
                int xx = x + kx - 1;
                if (xx < 0 || xx >= 20) continue;
                s1 += r1[xx * DG_CH] * ww1[kx];
                s2 += r2[xx * DG_CH] * ww2[kx];
            }
        }
        float ge = 0.5f * s1 * (1.0f + erff(s1 * 0.70710678118654752f));
        int y = y0 + yl;
        Y2H[((size_t)(b * NTOK + y * 20 + x)) * 512 + ch0 + ch] =
            __float2bfloat16(ge * s2 * ses[ch]);
    }
}

// ---------------- launcher ----------------
extern "C" void kernel_launch(void* const* d_in, const int* in_sizes, int n_in,
                              void* d_out, int out_size) {
    const float* src    = (const float*)d_in[0];
    const float* qg_w   = (const float*)d_in[1];
    const float* qg_b   = (const float*)d_in[2];
    const float* kv_w   = (const float*)d_in[3];
    const float* kv_b   = (const float*)d_in[4];
    const float* proj_w = (const float*)d_in[5];
    const float* proj_b = (const float*)d_in[6];
    const float* dwc_w  = (const float*)d_in[7];
    const float* dwc_b  = (const float*)d_in[8];
    const float* power  = (const float*)d_in[9];
    const float* scale  = (const float*)d_in[10];
    const float* pos    = (const float*)d_in[11];
    const float* pin_w  = (const float*)d_in[12];
    const float* dw_w   = (const float*)d_in[13];
    const float* se_w   = (const float*)d_in[14];
    const float* pout_w = (const float*)d_in[15];
    const float* ln1_w  = (const float*)d_in[16];
    const float* ln1_b  = (const float*)d_in[17];
    const float* ln2_w  = (const float*)d_in[18];
    const float* ln2_b  = (const float*)d_in[19];
    float* out = (float*)d_out;

    float* scr = nullptr;
    cudaGetSymbolAddress((void**)&scr, d_scratch);

    float* XT   = scr + O_XT;
    float* G    = scr + O_G;
    float* QP   = scr + O_QP;
    float* QN   = scr + O_QN;
    float* KP   = scr + O_KP;
    float* KN   = scr + O_KN;
    float* V    = scr + O_V;
    float* VD   = scr + O_VD;
    float* KM   = scr + O_KM;
    float* KVS  = scr + O_KVS;
    float* KVO  = scr + O_KVO;
    __nv_bfloat16* OUT2H = (__nv_bfloat16*)(scr + O_OUT2H);
    float* S    = scr + O_S;
    __nv_bfloat16* SH = (__nv_bfloat16*)(scr + O_SH);
    float* Y    = scr + O_Y;
    __nv_bfloat16* Y2H = (__nv_bfloat16*)(scr + O_Y2H);
    float* TMP  = scr + O_TMP;
    float* SE   = scr + O_SE;
    float* INV  = scr + O_INV;
    float* PW   = scr + O_PW;
    __nv_bfloat16* WPJH = (__nv_bfloat16*)(scr + O_WPJH);
    __nv_bfloat16* WPIH = (__nv_bfloat16*)(scr + O_WPIH);
    __nv_bfloat16* WPOH = (__nv_bfloat16*)(scr + O_WPOH);

    static bool attr_set = false;
    if (!attr_set) {
        cudaFuncSetAttribute(gemm_qgkv, cudaFuncAttributeMaxDynamicSharedMemorySize, SMEM_GEMM);
        cudaFuncSetAttribute(gemm_bf, cudaFuncAttributeMaxDynamicSharedMemorySize, SMEM_GBF);
        cudaFuncSetAttribute(gemm_bf_ln<256,true>,  cudaFuncAttributeMaxDynamicSharedMemorySize, SMEM_GBLN);
        cudaFuncSetAttribute(gemm_bf_ln<512,false>, cudaFuncAttributeMaxDynamicSharedMemorySize, SMEM_GBLN);
        cudaFuncSetAttribute(k_dw_glu, cudaFuncAttributeMaxDynamicSharedMemorySize, SMEM_DG);
        attr_set = true;
    }

    // 1. params + weight conversion
    k_prep<<<1, 256>>>(scale, power, INV, PW);
    k_cvtw<<<256, 256>>>(proj_w, WPJH, 256*256, pin_w, WPIH, 1024*256, pout_w, WPOH, 256*512);
    // 2. src -> token-major
    k_tr_src<<<dim3(13, 8, BATCH), dim3(32, 32)>>>(src, XT);
    // 3. merged qg + kv GEMMs (tf32, fused pow epilogues)
    gemm_qgkv<<<dim3(4, 200, 2), 256, SMEM_GEMM>>>(XT, qg_w, qg_b, kv_w, kv_b,
        pos, INV, PW, QP, QN, G, KP, KN, V);
    // 4. fused: reductions + dwc5x5 + SE
    k_fused<<<1600, 256>>>(KP, KN, V, KM, KVS, KVO, dwc_w, dwc_b, VD, src, se_w, SE);
    // 5. attention output + vd + gate -> bf16
    k_attn_out<<<512, 256>>>(QP, QN, KM, KVS, KVO, VD, G, OUT2H);
    // 6. proj + residual + LN1 (bf16 mma) -> S fp32 + SH bf16
    gemm_bf_ln<256,true><<<200, 512, SMEM_GBLN>>>(OUT2H, WPJH, proj_b, XT, ln1_w, ln1_b, S, SH);
    // 7. pin (bf16 mma) -> Y fp32
    gemm_bf<<<dim3(8, 200), 256, SMEM_GBF>>>(SH, WPIH, Y, TOKS, 1024, 256);
    // 8. dw3x3 + glu + se -> Y2 bf16
    k_dw_glu<<<dim3(4, 4, BATCH), 256, SMEM_DG>>>(Y, dw_w, SE, Y2H);
    // 9. pout + residual + LN2 (bf16 mma) -> TMP
    gemm_bf_ln<512,false><<<200, 512, SMEM_GBLN>>>(Y2H, WPOH, nullptr, S, ln2_w, ln2_b, TMP, nullptr);
    // 10. transpose to NCHW output
    k_tr_out<<<dim3(13, 8, BATCH), dim3(32, 32)>>>(TMP, out);
}

// round 8
// speedup vs baseline: 2.1991x; 1.1844x over previous
#include <cuda_runtime.h>
#include <cuda_bf16.h>
#include <math.h>
#include <stdint.h>

// ---------------- problem constants ----------------
#define BATCH 64
#define CCH   256
#define NTOK  400
#define TOKS  (BATCH*NTOK) // 25600

// ---------------- scratch layout (float units) ----------------
constexpr size_t O_XT    = 0;                          // fp32 TOKS*256
constexpr size_t O_XTH   = O_XT    + (size_t)TOKS*256; // bf16 TOKS*256
constexpr size_t O_G     = O_XTH   + (size_t)TOKS*128; // bf16 TOKS*256
constexpr size_t O_QP    = O_G     + (size_t)TOKS*128; // bf16
constexpr size_t O_QN    = O_QP    + (size_t)TOKS*128;
constexpr size_t O_KP    = O_QN    + (size_t)TOKS*128;
constexpr size_t O_KN    = O_KP    + (size_t)TOKS*128;
constexpr size_t O_V     = O_KN    + (size_t)TOKS*128; // fp32
constexpr size_t O_VD    = O_V     + (size_t)TOKS*256; // fp32
constexpr size_t O_KM    = O_VD    + (size_t)TOKS*256;
constexpr size_t O_KVS   = O_KM    + (size_t)512*64;
constexpr size_t O_KVO   = O_KVS   + (size_t)512*1024;
constexpr size_t O_OUT2H = O_KVO   + (size_t)512*1024; // bf16 TOKS*256
constexpr size_t O_S     = O_OUT2H + (size_t)TOKS*128; // fp32
constexpr size_t O_SH    = O_S     + (size_t)TOKS*256; // bf16
constexpr size_t O_YH    = O_SH    + (size_t)TOKS*128; // bf16 TOKS*1024
constexpr size_t O_Y2H   = O_YH    + (size_t)TOKS*512; // bf16 TOKS*512
constexpr size_t O_TMP   = O_Y2H   + (size_t)TOKS*256; // fp32
constexpr size_t O_SE    = O_TMP   + (size_t)TOKS*256;
constexpr size_t O_INV   = O_SE    + (size_t)BATCH*512;
constexpr size_t O_PW    = O_INV   + 256;
constexpr size_t O_WPJH  = O_PW    + 256;               // bf16 256*256
constexpr size_t O_WPIH  = O_WPJH  + 32768;             // bf16 1024*256
constexpr size_t O_WPOH  = O_WPIH  + 131072;            // bf16 256*512
constexpr size_t O_WQH   = O_WPOH  + 65536;             // bf16 512*256
constexpr size_t O_WKH   = O_WQH   + 65536;             // bf16 512*256
constexpr size_t SCR_TOTAL = O_WKH + 65536;

__device__ __align__(256) float d_scratch[SCR_TOTAL];

// =======================================================================
// helpers
// =======================================================================
__device__ __forceinline__ uint32_t smem_u32(const void* p) {
    uint32_t a;
    asm("{ .reg .u64 t; cvta.to.shared.u64 t, %1; cvt.u32.u64 %0, t; }" : "=r"(a) : "l"(p));
    return a;
}
__device__ __forceinline__ void cp16(uint32_t s, const void* g) {
    asm volatile("cp.async.ca.shared.global [%0], [%1], 16;" :: "r"(s), "l"(g));
}
#define CP_COMMIT() asm volatile("cp.async.commit_group;" ::: "memory")
#define CP_WAIT(n)  asm volatile("cp.async.wait_group %0;" :: "n"(n) : "memory")

__device__ __forceinline__ void mma_bf16(float* d, const uint32_t* a, const uint32_t* b) {
    asm volatile(
        "mma.sync.aligned.m16n8k16.row.col.f32.bf16.bf16.f32 "
        "{%0,%1,%2,%3}, {%4,%5,%6,%7}, {%8,%9}, {%0,%1,%2,%3};"
        : "+f"(d[0]), "+f"(d[1]), "+f"(d[2]), "+f"(d[3])
        : "r"(a[0]), "r"(a[1]), "r"(a[2]), "r"(a[3]), "r"(b[0]), "r"(b[1]));
}

// bf16 smem geometry: 64 bf16 per row chunk + 16B pad
constexpr int HROWB = 144;                 // bytes per smem row
constexpr int HROWW = 36;                  // words per row
constexpr int HB_TILE_B = 128 * HROWB;     // 18432
constexpr int HB_BUF_B  = 2 * HB_TILE_B;   // 36864
constexpr int SMEM_GBF  = 2 * HB_BUF_B;    // 73728

// =======================================================================
// gemm_qgkv_bf: merged qg + kv GEMMs (bf16). grid (4, 200, 2).
// z=0: qg -> QP/QN (pow, bf16), G (bf16). z=1: kv -> KP/KN (pow, bf16), V (fp32).
// M=TOKS, N=512, K=256. CTA tile 128x128.
// =======================================================================
__global__ __launch_bounds__(256, 2)
void gemm_qgkv_bf(const __nv_bfloat16* __restrict__ A,
                  const __nv_bfloat16* __restrict__ wq, const float* __restrict__ bq,
                  const __nv_bfloat16* __restrict__ wk, const float* __restrict__ bk,
                  const float* __restrict__ pos,
                  const float* __restrict__ invsc, const float* __restrict__ pw,
                  __nv_bfloat16* __restrict__ QP, __nv_bfloat16* __restrict__ QN,
                  __nv_bfloat16* __restrict__ G,
                  __nv_bfloat16* __restrict__ KP, __nv_bfloat16* __restrict__ KN,
                  float* __restrict__ V) {
    const int K = 256;
    extern __shared__ float sm[];
    const uint32_t sbase = smem_u32(sm);
    char* cbase = (char*)sm;
    const int t = threadIdx.x, lane = t & 31, wid = t >> 5;
    const int wm = (wid >> 2) * 64;
    const int wn = (wid & 3) * 32;
    const int bm = blockIdx.y * 128, bn = blockIdx.x * 128;
    const int g4 = lane >> 2, l4 = lane & 3;
    const bool isKV = (blockIdx.z != 0);
    const __nv_bfloat16* Bw = isKV ? wk : wq;
    const float* bias = isKV ? bk : bq;

    auto load_chunk = [&](int ch, int buf) {
        int k0 = ch << 6;
        uint32_t sb = sbase + (uint32_t)buf * HB_BUF_B;
#pragma unroll
        for (int i = 0; i < 8; i++) {
            int o = t + i * 256;
            int isB = o >> 10;
            int row = (o & 1023) >> 3;
            int seg = o & 7;
            const __nv_bfloat16* g = (isB ? Bw + (size_t)(bn + row) * K
                                          : A  + (size_t)(bm + row) * K) + k0 + seg * 8;
            uint32_t s = sb + (uint32_t)(isB * HB_TILE_B + row * HROWB + seg * 16);
            cp16(s, g);
        }
        CP_COMMIT();
    };

    float acc[4][4][4];
#pragma unroll
    for (int mi = 0; mi < 4; mi++)
#pragma unroll
        for (int ni = 0; ni < 4; ni++)
#pragma unroll
            for (int k = 0; k < 4; k++) acc[mi][ni][k] = 0.0f;

    load_chunk(0, 0);
    load_chunk(1, 1);
    const int NC = 4;
    for (int ch = 0; ch < NC; ch++) {
        if (ch + 1 < NC) { CP_WAIT(1); } else { CP_WAIT(0); }
        __syncthreads();
        const uint32_t* Ab = (const uint32_t*)(cbase + (ch & 1) * HB_BUF_B);
        const uint32_t* Bb = (const uint32_t*)(cbase + (ch & 1) * HB_BUF_B + HB_TILE_B);
#pragma unroll
        for (int s = 0; s < 4; s++) {
            int c0 = s * 8 + l4;
            uint32_t ah[4][4], bh[4][2];
#pragma unroll
            for (int mi = 0; mi < 4; mi++) {
                int r0 = wm + mi * 16 + g4;
                ah[mi][0] = Ab[r0 * HROWW + c0];
                ah[mi][1] = Ab[(r0 + 8) * HROWW + c0];
                ah[mi][2] = Ab[r0 * HROWW + c0 + 4];
                ah[mi][3] = Ab[(r0 + 8) * HROWW + c0 + 4];
            }
#pragma unroll
            for (int ni = 0; ni < 4; ni++) {
                int n0 = wn + ni * 8 + g4;
                bh[ni][0] = Bb[n0 * HROWW + c0];
                bh[ni][1] = Bb[n0 * HROWW + c0 + 4];
            }
#pragma unroll
            for (int mi = 0; mi < 4; mi++)
#pragma unroll
                for (int ni = 0; ni < 4; ni++)
                    mma_bf16(acc[mi][ni], ah[mi], bh[ni]);
        }
        __syncthreads();
        if (ch + 2 < NC) load_chunk(ch + 2, ch & 1);
    }

    bool first_half = (bn < 256);
#pragma unroll
    for (int mi = 0; mi < 4; mi++) {
#pragma unroll
        for (int half = 0; half < 2; half++) {
            int r = bm + wm + mi * 16 + g4 + half * 8;
            int tok = r % NTOK;
#pragma unroll
            for (int ni = 0; ni < 4; ni++) {
                int cb = bn + wn + ni * 8 + 2 * l4;
                float v0 = acc[mi][ni][half * 2 + 0] + bias[cb];
                float v1 = acc[mi][ni][half * 2 + 1] + bias[cb + 1];
                if (first_half) {
                    float xp0 = 0.f, xn0 = 0.f, xp1 = 0.f, xn1 = 0.f;
#pragma unroll
                    for (int j = 0; j < 2; j++) {
                        int ccol = cb + j;
                        float v = j ? v1 : v0;
                        float x = isKV ? (v + pos[(size_t)tok * 256 + ccol]) * invsc[ccol]
                                       : v * invsc[ccol];
                        float p = pw[ccol];
                        float xp = 0.f, xn = 0.f;
                        if (x > 0.f)      xp = __powf(fmaxf(x, 1e-30f), p);
                        else if (x < 0.f) xn = __powf(fmaxf(-x, 1e-30f), p);
                        if (j) { xp1 = xp; xn1 = xn; } else { xp0 = xp; xn0 = xn; }
                    }
                    __nv_bfloat16* P1 = isKV ? KP : QP;
                    __nv_bfloat16* P2 = isKV ? KN : QN;
                    *(__nv_bfloat162*)&P1[(size_t)r * 256 + cb] =
                        __floats2bfloat162_rn(xp0, xp1);
                    *(__nv_bfloat162*)&P2[(size_t)r * 256 + cb] =
                        __floats2bfloat162_rn(xn0, xn1);
                } else {
                    int cc = cb - 256;
                    if (isKV) {
                        *(float2*)&V[(size_t)r * 256 + cc] = make_float2(v0, v1);
                    } else {
                        *(__nv_bfloat162*)&G[(size_t)r * 256 + cc] =
                            __floats2bfloat162_rn(v0, v1);
                    }
                }
            }
        }
    }
}

// =======================================================================
// gemm_bf: bf16 GEMM. OB: write bf16 output. 128x128 tile, 256 thr.
// =======================================================================
template<bool OB>
__global__ __launch_bounds__(256, 2)
void gemm_bf(const __nv_bfloat16* __restrict__ A, const __nv_bfloat16* __restrict__ Bw,
             void* __restrict__ Cv, int M, int N, int K) {
    extern __shared__ float sm[];
    const uint32_t sbase = smem_u32(sm);
    char* cbase = (char*)sm;
    const int t = threadIdx.x, lane = t & 31, wid = t >> 5;
    const int wm = (wid >> 2) * 64;
    const int wn = (wid & 3) * 32;
    const int bm = blockIdx.y * 128, bn = blockIdx.x * 128;
    const int g4 = lane >> 2, l4 = lane & 3;
    const int NC = K >> 6;

    auto load_chunk = [&](int ch, int buf) {
        int k0 = ch << 6;
        uint32_t sb = sbase + (uint32_t)buf * HB_BUF_B;
#pragma unroll
        for (int i = 0; i < 8; i++) {
            int o = t + i * 256;
            int isB = o >> 10;
            int row = (o & 1023) >> 3;
            int seg = o & 7;
            const __nv_bfloat16* g = (isB ? Bw + (size_t)(bn + row) * K
                                          : A  + (size_t)(bm + row) * K) + k0 + seg * 8;
            uint32_t s = sb + (uint32_t)(isB * HB_TILE_B + row * HROWB + seg * 16);
            cp16(s, g);
        }
        CP_COMMIT();
    };

    float acc[4][4][4];
#pragma unroll
    for (int mi = 0; mi < 4; mi++)
#pragma unroll
        for (int ni = 0; ni < 4; ni++)
#pragma unroll
            for (int k = 0; k < 4; k++) acc[mi][ni][k] = 0.0f;

    load_chunk(0, 0);
    if (NC > 1) load_chunk(1, 1);

    for (int ch = 0; ch < NC; ch++) {
        if (ch + 1 < NC) { CP_WAIT(1); } else { CP_WAIT(0); }
        __syncthreads();
        const uint32_t* Ab = (const uint32_t*)(cbase + (ch & 1) * HB_BUF_B);
        const uint32_t* Bb = (const uint32_t*)(cbase + (ch & 1) * HB_BUF_B + HB_TILE_B);
#pragma unroll
        for (int s = 0; s < 4; s++) {
            int c0 = s * 8 + l4;
            uint32_t ah[4][4], bh[4][2];
#pragma unroll
            for (int mi = 0; mi < 4; mi++) {
                int r0 = wm + mi * 16 + g4;
                ah[mi][0] = Ab[r0 * HROWW + c0];
                ah[mi][1] = Ab[(r0 + 8) * HROWW + c0];
                ah[mi][2] = Ab[r0 * HROWW + c0 + 4];
                ah[mi][3] = Ab[(r0 + 8) * HROWW + c0 + 4];
            }
#pragma unroll
            for (int ni = 0; ni < 4; ni++) {
                int n0 = wn + ni * 8 + g4;
                bh[ni][0] = Bb[n0 * HROWW + c0];
                bh[ni][1] = Bb[n0 * HROWW + c0 + 4];
            }
#pragma unroll
            for (int mi = 0; mi < 4; mi++)
#pragma unroll
                for (int ni = 0; ni < 4; ni++)
                    mma_bf16(acc[mi][ni], ah[mi], bh[ni]);
        }
        __syncthreads();
        if (ch + 2 < NC) load_chunk(ch + 2, ch & 1);
    }

#pragma unroll
    for (int mi = 0; mi < 4; mi++) {
        int r0 = bm + wm + mi * 16 + g4;
#pragma unroll
        for (int ni = 0; ni < 4; ni++) {
            int cb = bn + wn + ni * 8 + 2 * l4;
            if (OB) {
                __nv_bfloat16* C = (__nv_bfloat16*)Cv;
                *(__nv_bfloat162*)&C[(size_t)r0 * N + cb] =
                    __floats2bfloat162_rn(acc[mi][ni][0], acc[mi][ni][1]);
                *(__nv_bfloat162*)&C[(size_t)(r0 + 8) * N + cb] =
                    __floats2bfloat162_rn(acc[mi][ni][2], acc[mi][ni][3]);
            } else {
                float* C = (float*)Cv;
                *(float2*)&C[(size_t)r0 * N + cb]       = make_float2(acc[mi][ni][0], acc[mi][ni][1]);
                *(float2*)&C[(size_t)(r0 + 8) * N + cb] = make_float2(acc[mi][ni][2], acc[mi][ni][3]);
            }
        }
    }
}

// =======================================================================
// gemm_bf_ln: OUT = LN( RES + A@Bw^T (+bias) ), N=256, 512 thr.
// =======================================================================
constexpr int HL_TA_B  = 128 * HROWB;
constexpr int HL_BUF_B = (128 + 256) * HROWB;
constexpr int SMEM_GBLN = 2 * HL_BUF_B;

template<int KD, bool WH>
__global__ __launch_bounds__(512)
void gemm_bf_ln(const __nv_bfloat16* __restrict__ A, const __nv_bfloat16* __restrict__ Bw,
                const float* __restrict__ bias, const float* __restrict__ RES,
                const float* __restrict__ lw, const float* __restrict__ lb,
                float* __restrict__ OUT, __nv_bfloat16* __restrict__ OUTH) {
    const int N = 256;
    extern __shared__ float sm[];
    const uint32_t sbase = smem_u32(sm);
    char* cbase = (char*)sm;
    const int t = threadIdx.x, lane = t & 31, wid = t >> 5;
    const int wm = (wid >> 2) * 32;
    const int wn = (wid & 3) * 64;
    const int bm = blockIdx.x * 128;
    const int g4 = lane >> 2, l4 = lane & 3;
    const int NC = KD >> 6;

    auto load_chunk = [&](int ch, int buf) {
        int k0 = ch << 6;
        uint32_t sb = sbase + (uint32_t)buf * HL_BUF_B;
#pragma unroll
        for (int i = 0; i < 6; i++) {
            int o = t + i * 512;
            bool isB = o >= 1024;
            int row = isB ? ((o - 1024) >> 3) : (o >> 3);
            int seg = o & 7;
            const __nv_bfloat16* g = (isB ? Bw + (size_t)row * KD
                                          : A  + (size_t)(bm + row) * KD) + k0 + seg * 8;
            uint32_t s = sb + (uint32_t)((isB ? HL_TA_B : 0) + row * HROWB + seg * 16);
            cp16(s, g);
        }
        CP_COMMIT();
    };

    float acc[2][8][4];
#pragma unroll
    for (int mi = 0; mi < 2; mi++)
#pragma unroll
        for (int ni = 0; ni < 8; ni++)
#pragma unroll
            for (int k = 0; k < 4; k++) acc[mi][ni][k] = 0.0f;

    load_chunk(0, 0);
    if (NC > 1) load_chunk(1, 1);

    for (int ch = 0; ch < NC; ch++) {
        if (ch + 1 < NC) { CP_WAIT(1); } else { CP_WAIT(0); }
        __syncthreads();
        const uint32_t* Ab = (const uint32_t*)(cbase + (ch & 1) * HL_BUF_B);
        const uint32_t* Bb = (const uint32_t*)(cbase + (ch & 1) * HL_BUF_B + HL_TA_B);
#pragma unroll
        for (int s = 0; s < 4; s++) {
            int c0 = s * 8 + l4;
            uint32_t af[2][4], bf[8][2];
#pragma unroll
            for (int mi = 0; mi < 2; mi++) {
                int r0 = wm + mi * 16 + g4;
                af[mi][0] = Ab[r0 * HROWW + c0];
                af[mi][1] = Ab[(r0 + 8) * HROWW + c0];
                af[mi][2] = Ab[r0 * HROWW + c0 + 4];
                af[mi][3] = Ab[(r0 + 8) * HROWW + c0 + 4];
            }
#pragma unroll
            for (int ni = 0; ni < 8; ni++) {
                int n0 = wn + ni * 8 + g4;
                bf[ni][0] = Bb[n0 * HROWW + c0];
                bf[ni][1] = Bb[n0 * HROWW + c0 + 4];
            }
#pragma unroll
            for (int mi = 0; mi < 2; mi++)
#pragma unroll
                for (int ni = 0; ni < 8; ni++)
                    mma_bf16(acc[mi][ni], af[mi], bf[ni]);
        }
        __syncthreads();
        if (ch + 2 < NC) load_chunk(ch + 2, ch & 1);
    }

    __syncthreads();
    float* ssum = sm;
    float* ssq  = sm + 512;

#pragma unroll
    for (int mi = 0; mi < 2; mi++)
#pragma unroll
        for (int half = 0; half < 2; half++) {
            int r = bm + wm + mi * 16 + g4 + half * 8;
#pragma unroll
            for (int ni = 0; ni < 8; ni++)
#pragma unroll
                for (int j = 0; j < 2; j++) {
                    int c = wn + ni * 8 + 2 * l4 + j;
                    float b = bias ? bias[c] : 0.f;
                    acc[mi][ni][half * 2 + j] += b + RES[(size_t)r * N + c];
                }
        }
#pragma unroll
    for (int mi = 0; mi < 2; mi++)
#pragma unroll
        for (int half = 0; half < 2; half++) {
            float s = 0.f, q = 0.f;
#pragma unroll
            for (int ni = 0; ni < 8; ni++)
#pragma unroll
                for (int j = 0; j < 2; j++) {
                    float v = acc[mi][ni][half * 2 + j];
                    s += v; q += v * v;
                }
            s += __shfl_xor_sync(0xffffffffu, s, 1);
            s += __shfl_xor_sync(0xffffffffu, s, 2);
            q += __shfl_xor_sync(0xffffffffu, q, 1);
            q += __shfl_xor_sync(0xffffffffu, q, 2);
            if (l4 == 0) {
                int lr = wm + mi * 16 + g4 + half * 8;
                ssum[(wid & 3) * 128 + lr] = s;
                ssq[(wid & 3) * 128 + lr]  = q;
            }
        }
    __syncthreads();
#pragma unroll
    for (int mi = 0; mi < 2; mi++)
#pragma unroll
        for (int half = 0; half < 2; half++) {
            int lr = wm + mi * 16 + g4 + half * 8;
            float s = ssum[lr] + ssum[128 + lr] + ssum[256 + lr] + ssum[384 + lr];
            float q = ssq[lr]  + ssq[128 + lr]  + ssq[256 + lr]  + ssq[384 + lr];
            float mean = s * (1.0f / 256.0f);
            float var  = q * (1.0f / 256.0f) - mean * mean;
            float inv  = rsqrtf(var + 1e-6f);
            int r = bm + lr;
#pragma unroll
            for (int ni = 0; ni < 8; ni++)
#pragma unroll
                for (int j = 0; j < 2; j++) {
                    int c = wn + ni * 8 + 2 * l4 + j;
                    float v = acc[mi][ni][half * 2 + j];
                    float o = lw[c] * (v - mean) * inv + lb[c];
                    OUT[(size_t)r * N + c] = o;
                    if (WH) OUTH[(size_t)r * N + c] = __float2bfloat16(o);
                }
        }
}

// ---------------- param prep ----------------
__global__ void k_prep(const float* __restrict__ scale, const float* __restrict__ power,
                       float* __restrict__ invsc, float* __restrict__ pw) {
    int c = threadIdx.x;
    float sp = log1pf(expf(scale[c]));
    invsc[c] = 1.0f / sp;
    pw[c] = 1.0f + 4.0f / (1.0f + expf(-power[c]));
}

// ---------------- weight -> bf16 convert (5 tensors) ----------------
__global__ void k_cvtw(const float* __restrict__ p1, __nv_bfloat16* __restrict__ o1, int n1,
                       const float* __restrict__ p2, __nv_bfloat16* __restrict__ o2, int n2,
                       const float* __restrict__ p3, __nv_bfloat16* __restrict__ o3, int n3,
                       const float* __restrict__ p4, __nv_bfloat16* __restrict__ o4, int n4,
                       const float* __restrict__ p5, __nv_bfloat16* __restrict__ o5, int n5) {
    int total = n1 + n2 + n3 + n4 + n5;
    for (int i = blockIdx.x * blockDim.x + threadIdx.x; i < total; i += gridDim.x * blockDim.x) {
        int r = i;
        if (r < n1) { o1[r] = __float2bfloat16(p1[r]); continue; } r -= n1;
        if (r < n2) { o2[r] = __float2bfloat16(p2[r]); continue; } r -= n2;
        if (r < n3) { o3[r] = __float2bfloat16(p3[r]); continue; } r -= n3;
        if (r < n4) { o4[r] = __float2bfloat16(p4[r]); continue; } r -= n4;
        o5[r] = __float2bfloat16(p5[r]);
    }
}

// ---------------- transpose (B,C,400) -> (B,400,C) fp32 + bf16 ----------------
__global__ void k_tr_src(const float* __restrict__ src, float* __restrict__ XT,
                         __nv_bfloat16* __restrict__ XTH) {
    __shared__ float tile[32][33];
    int b = blockIdx.z, cb = blockIdx.y * 32, nb = blockIdx.x * 32;
    int tx = threadIdx.x, ty = threadIdx.y;
    int n = nb + tx, c = cb + ty;
    if (n < NTOK) tile[ty][tx] = src[(size_t)b*CCH*NTOK + (size_t)c*NTOK + n];
    __syncthreads();
    n = nb + ty; c = cb + tx;
    if (n < NTOK) {
        float v = tile[tx][ty];
        size_t o = ((size_t)b*NTOK + n)*CCH + c;
        XT[o] = v;
        XTH[o] = __float2bfloat16(v);
    }
}

// ---------------- transpose (B,400,C) -> (B,C,400) ----------------
__global__ void k_tr_out(const float* __restrict__ TMP, float* __restrict__ OUT) {
    __shared__ float tile[32][33];
    int b = blockIdx.z, cb = blockIdx.y * 32, nb = blockIdx.x * 32;
    int tx = threadIdx.x, ty = threadIdx.y;
    int n = nb + ty, c = cb + tx;
    if (n < NTOK) tile[ty][tx] = TMP[((size_t)b*NTOK + n)*CCH + c];
    __syncthreads();
    c = cb + ty; n = nb + tx;
    if (n < NTOK) OUT[(size_t)b*CCH*NTOK + (size_t)c*NTOK + n] = tile[tx][ty];
}

// =======================================================================
// k_fused: [0,512) per-(b,h) reductions; [512,1536) dwc5x5; [1536,1600) SE
// =======================================================================
__global__ __launch_bounds__(256)
void k_fused(const __nv_bfloat16* __restrict__ KP, const __nv_bfloat16* __restrict__ KN,
             const float* __restrict__ V,
             float* __restrict__ KM, float* __restrict__ KVS, float* __restrict__ KVO,
             const float* __restrict__ dwcw, const float* __restrict__ dwcb,
             float* __restrict__ VD,
             const float* __restrict__ src, const float* __restrict__ sew,
             float* __restrict__ SE) {
    __shared__ float fsm[14*640 + 800 + 32];
    int bid = blockIdx.x;
    int t = threadIdx.x;

    if (bid < 512) {
        float* kc_s = fsm;
        float* v_s  = fsm + 1024;
        int bh = bid, b = bh >> 3, h = bh & 7;
        int j = t >> 2, e0 = (t & 3) << 2;
        float accs[4] = {0,0,0,0}, acco[4] = {0,0,0,0}, accm = 0.f;
        for (int n0 = 0; n0 < NTOK; n0 += 16) {
            for (int idx = t; idx < 16*64; idx += 256) {
                int nl = idx >> 6, jj = idx & 63;
                size_t base = ((size_t)(b*NTOK + n0 + nl))*256 + h*32 + (jj & 31);
                kc_s[idx] = __bfloat162float((jj < 32) ? KP[base] : KN[base]);
            }
            for (int idx = t; idx < 16*32; idx += 256) {
                int nl = idx >> 5, ee = idx & 31;
                size_t base = ((size_t)(b*NTOK + n0 + nl))*256 + (ee < 16 ? h*16 + ee : 128 + h*16 + ee - 16);
                v_s[idx] = V[base];
            }
            __syncthreads();
#pragma unroll
            for (int nl = 0; nl < 16; nl++) {
                float kcv = kc_s[nl*64 + j];
                accm += kcv;
#pragma unroll
                for (int q = 0; q < 4; q++) {
                    accs[q] += kcv * v_s[nl*32 + e0 + q];
                    acco[q] += kcv * v_s[nl*32 + 16 + e0 + q];
                }
            }
            __syncthreads();
        }
        const float invN = 1.0f / (float)NTOK;
        size_t ob = (size_t)bh*1024 + (size_t)j*16 + e0;
#pragma unroll
        for (int q = 0; q < 4; q++) { KVS[ob+q] = accs[q]*invN; KVO[ob+q] = acco[q]*invN; }
        if ((t & 3) == 0) KM[(size_t)bh*64 + j] = accm * invN;
    } else if (bid < 1536) {
        float* tile = fsm;
        float* ws   = fsm + 14*640;
        float* bs   = ws + 800;
        int blk = bid - 512;
        int half = blk & 1, g = (blk >> 1) & 7, b = blk >> 4;
        for (int i = t; i < 800; i += 256) ws[i] = dwcw[i];
        if (t < 32) bs[t] = dwcb[t];
        const float* Vb = V + (size_t)b*102400 + (size_t)g*12800;
        int r0 = half*10 - 2;
        for (int i = t; i < 14*640; i += 256) {
            int rr = i / 640, rem = i - rr*640;
            int r = r0 + rr;
            tile[i] = (r >= 0 && r < 20) ? Vb[r*640 + rem] : 0.0f;
        }
        __syncthreads();
        for (int oi = t; oi < 10*640; oi += 256) {
            int yl = oi / 640, rem = oi - yl*640;
            int x = rem >> 5, dd = rem & 31;
            int lrow = yl + 2;
            float acc = bs[dd];
#pragma unroll
            for (int ky = 0; ky < 5; ky++) {
#pragma unroll
                for (int kx = 0; kx < 5; kx++) {
                    int xx = x + kx - 2;
                    if (xx >= 0 && xx < 20)
                        acc += tile[(lrow + ky - 2)*640 + xx*32 + dd] * ws[dd*25 + ky*5 + kx];
                }
            }
            int y = half*10 + yl;
            VD[(size_t)b*102400 + (size_t)g*12800 + (size_t)y*640 + rem] = acc;
        }
    } else {
        float* smv = fsm;
        int b = bid - 1536;
        int w = t >> 5, lane = t & 31;
        for (int ci = 0; ci < 32; ci++) {
            int c = w*32 + ci;
            const float* p = src + (size_t)b*102400 + (size_t)c*400;
            float s = 0.f;
            for (int n = lane; n < 400; n += 32) s += p[n];
#pragma unroll
            for (int off = 16; off; off >>= 1) s += __shfl_xor_sync(0xffffffffu, s, off);
            if (lane == 0) smv[c] = s * (1.0f/400.0f);
        }
        __syncthreads();
        for (int o = t; o < 512; o += 256) {
            const float* wr = sew + (size_t)o*256;
            float acc = 0.f;
            for (int c = 0; c < 256; c++) acc += wr[c] * smv[c];
            SE[(size_t)b*512 + o] = 1.0f / (1.0f + expf(-acc));
        }
    }
}

// ---------------- attention output + vd + gate (bf16 in/out) ----------------
__global__ __launch_bounds__(256)
void k_attn_out(const __nv_bfloat16* __restrict__ QP, const __nv_bfloat16* __restrict__ QN,
                const float* __restrict__ KM, const float* __restrict__ KVS,
                const float* __restrict__ KVO, const float* __restrict__ VD,
                const __nv_bfloat16* __restrict__ G, __nv_bfloat16* __restrict__ OUT2H) {
    int bh = blockIdx.x, b = bh >> 3, h = bh & 7;
    __shared__ float km_s[64];
    __shared__ float kvb[64][32];
    __shared__ float qps[8][32], qns[8][32];
    int t = threadIdx.x, w = t >> 5, d = t & 31;
    for (int idx = t; idx < 64; idx += 256) km_s[idx] = KM[(size_t)bh*64 + idx];
    for (int idx = t; idx < 2048; idx += 256) {
        int j = idx >> 5, col = idx & 31;
        kvb[j][col] = (col < 16) ? KVS[(size_t)bh*1024 + j*16 + col]
                                 : KVO[(size_t)bh*1024 + j*16 + (col - 16)];
    }
    __syncthreads();
    bool sim = (d < 16);
    for (int n0 = 0; n0 < NTOK; n0 += 8) {
        int n = n0 + w;
        size_t tokbase = ((size_t)(b*NTOK + n)) * 256;
        float qp = __bfloat162float(QP[tokbase + h*32 + d]);
        float qn = __bfloat162float(QN[tokbase + h*32 + d]);
        qps[w][d] = qp; qns[w][d] = qn;
        __syncwarp();
        float d1 = qp*km_s[d] + qn*km_s[32 + d];
        float d2 = qn*km_s[d] + qp*km_s[32 + d];
#pragma unroll
        for (int off = 16; off; off >>= 1) {
            d1 += __shfl_xor_sync(0xffffffffu, d1, off);
            d2 += __shfl_xor_sync(0xffffffffu, d2, off);
        }
        float acc = 0.f;
#pragma unroll
        for (int j = 0; j < 32; j++) {
            float a = qps[w][j], bb = qns[w][j];
            float m1 = sim ? a : bb;
            float m2 = sim ? bb : a;
            acc += m1*kvb[j][d] + m2*kvb[32 + j][d];
        }
        float den = (sim ? d1 : d2) + 1e-6f;
        float val = acc / den;
        int c = h*32 + d;
        float vdv = VD[(size_t)b*102400 + (size_t)n*256 + c];
        float gg  = __bfloat162float(G[tokbase + c]);
        OUT2H[tokbase + c] = __float2bfloat16((val + vdv) * gg);
        __syncwarp();
    }
}

// ---------------- dw3x3 + GLU(gelu) + SE scale — SMEM tiled ----------------
constexpr int DG_CH  = 128;
constexpr int DG_TROW = 20 * DG_CH;
constexpr int DG_TILE = 7 * DG_TROW;
constexpr int SMEM_DG = (2 * DG_TILE + 2 * DG_CH * 9 + DG_CH) * 4;

__global__ __launch_bounds__(256)
void k_dw_glu(const __nv_bfloat16* __restrict__ Y, const float* __restrict__ dww,
              const float* __restrict__ SE, __nv_bfloat16* __restrict__ Y2H) {
    extern __shared__ float dsm[];
    float* s1t = dsm;
    float* s2t = dsm + DG_TILE;
    float* w1  = dsm + 2 * DG_TILE;
    float* w2  = w1 + DG_CH * 9;
    float* ses = w2 + DG_CH * 9;

    int cq = blockIdx.x, ys = blockIdx.y, b = blockIdx.z;
    int t = threadIdx.x;
    int ch0 = cq * DG_CH;
    int y0 = ys * 5;

    for (int i = t; i < DG_CH * 9; i += 256) {
        int ch = i / 9, k = i % 9;
        w1[i] = dww[(ch0 + ch) * 9 + k];
        w2[i] = dww[(512 + ch0 + ch) * 9 + k];
    }
    if (t < DG_CH) ses[t] = SE[(size_t)b * 512 + ch0 + t];

    for (int i = t; i < DG_TILE; i += 256) {
        int r = i / DG_TROW;
        int rem = i - r * DG_TROW;
        int x = rem >> 7, ch = rem & 127;
        int gy = y0 - 1 + r;
        float v1 = 0.f, v2 = 0.f;
        if (gy >= 0 && gy < 20) {
            size_t base = ((size_t)(b * NTOK + gy * 20 + x)) * 1024;
            v1 = __bfloat162float(Y[base + ch0 + ch]);
            v2 = __bfloat162float(Y[base + 512 + ch0 + ch]);
        }
        s1t[i] = v1; s2t[i] = v2;
    }
    __syncthreads();

    for (int oi = t; oi < 5 * DG_TROW; oi += 256) {
        int yl = oi / DG_TROW;
        int rem = oi - yl * DG_TROW;
        int x = rem >> 7, ch = rem & 127;
        float s1 = 0.f, s2 = 0.f;
#pragma unroll
        for (int ky = 0; ky < 3; ky++) {
            const float* r1 = s1t + (yl + ky) * DG_TROW + ch;
            const float* r2 = s2t + (yl + ky) * DG_TROW + ch;
            const float* ww1 = w1 + ch * 9 + ky * 3;
            const float* ww2 = w2 + ch * 9 + ky * 3;
#pragma unroll
            for (int kx = 0; kx < 3; kx++) {
                int xx = x + kx - 1;
                if (xx < 0 || xx >= 20) continue;
                s1 += r1[xx * DG_CH] * ww1[kx];
                s2 += r2[xx * DG_CH] * ww2[kx];
            }
        }
        float ge = 0.5f * s1 * (1.0f + erff(s1 * 0.70710678118654752f));
        int y = y0 + yl;
        Y2H[((size_t)(b * NTOK + y * 20 + x)) * 512 + ch0 + ch] =
            __float2bfloat16(ge * s2 * ses[ch]);
    }
}

// ---------------- launcher ----------------
extern "C" void kernel_launch(void* const* d_in, const int* in_sizes, int n_in,
                              void* d_out, int out_size) {
    const float* src    = (const float*)d_in[0];
    const float* qg_w   = (const float*)d_in[1];
    const float* qg_b   = (const float*)d_in[2];
    const float* kv_w   = (const float*)d_in[3];
    const float* kv_b   = (const float*)d_in[4];
    const float* proj_w = (const float*)d_in[5];
    const float* proj_b = (const float*)d_in[6];
    const float* dwc_w  = (const float*)d_in[7];
    const float* dwc_b  = (const float*)d_in[8];
    const float* power  = (const float*)d_in[9];
    const float* scale  = (const float*)d_in[10];
    const float* pos    = (const float*)d_in[11];
    const float* pin_w  = (const float*)d_in[12];
    const float* dw_w   = (const float*)d_in[13];
    const float* se_w   = (const float*)d_in[14];
    const float* pout_w = (const float*)d_in[15];
    const float* ln1_w  = (const float*)d_in[16];
    const float* ln1_b  = (const float*)d_in[17];
    const float* ln2_w  = (const float*)d_in[18];
    const float* ln2_b  = (const float*)d_in[19];
    float* out = (float*)d_out;

    float* scr = nullptr;
    cudaGetSymbolAddress((void**)&scr, d_scratch);

    float* XT   = scr + O_XT;
    __nv_bfloat16* XTH = (__nv_bfloat16*)(scr + O_XTH);
    __nv_bfloat16* G   = (__nv_bfloat16*)(scr + O_G);
    __nv_bfloat16* QP  = (__nv_bfloat16*)(scr + O_QP);
    __nv_bfloat16* QN  = (__nv_bfloat16*)(scr + O_QN);
    __nv_bfloat16* KP  = (__nv_bfloat16*)(scr + O_KP);
    __nv_bfloat16* KN  = (__nv_bfloat16*)(scr + O_KN);
    float* V    = scr + O_V;
    float* VD   = scr + O_VD;
    float* KM   = scr + O_KM;
    float* KVS  = scr + O_KVS;
    float* KVO  = scr + O_KVO;
    __nv_bfloat16* OUT2H = (__nv_bfloat16*)(scr + O_OUT2H);
    float* S    = scr + O_S;
    __nv_bfloat16* SH  = (__nv_bfloat16*)(scr + O_SH);
    __nv_bfloat16* YH  = (__nv_bfloat16*)(scr + O_YH);
    __nv_bfloat16* Y2H = (__nv_bfloat16*)(scr + O_Y2H);
    float* TMP  = scr + O_TMP;
    float* SE   = scr + O_SE;
    float* INV  = scr + O_INV;
    float* PW   = scr + O_PW;
    __nv_bfloat16* WPJH = (__nv_bfloat16*)(scr + O_WPJH);
    __nv_bfloat16* WPIH = (__nv_bfloat16*)(scr + O_WPIH);
    __nv_bfloat16* WPOH = (__nv_bfloat16*)(scr + O_WPOH);
    __nv_bfloat16* WQH  = (__nv_bfloat16*)(scr + O_WQH);
    __nv_bfloat16* WKH  = (__nv_bfloat16*)(scr + O_WKH);

    static bool attr_set = false;
    if (!attr_set) {
        cudaFuncSetAttribute(gemm_qgkv_bf, cudaFuncAttributeMaxDynamicSharedMemorySize, SMEM_GBF);
        cudaFuncSetAttribute(gemm_bf<true>, cudaFuncAttributeMaxDynamicSharedMemorySize, SMEM_GBF);
        cudaFuncSetAttribute(gemm_bf_ln<256,true>,  cudaFuncAttributeMaxDynamicSharedMemorySize, SMEM_GBLN);
        cudaFuncSetAttribute(gemm_bf_ln<512,false>, cudaFuncAttributeMaxDynamicSharedMemorySize, SMEM_GBLN);
        cudaFuncSetAttribute(k_dw_glu, cudaFuncAttributeMaxDynamicSharedMemorySize, SMEM_DG);
        attr_set = true;
    }

    // 1. params + weight conversion
    k_prep<<<1, 256>>>(scale, power, INV, PW);
    k_cvtw<<<256, 256>>>(proj_w, WPJH, 256*256, pin_w, WPIH, 1024*256,
                         pout_w, WPOH, 256*512, qg_w, WQH, 512*256, kv_w, WKH, 512*256);
    // 2. src -> token-major (fp32 + bf16)
    k_tr_src<<<dim3(13, 8, BATCH), dim3(32, 32)>>>(src, XT, XTH);
    // 3. merged qg + kv GEMMs (bf16, fused pow epilogues)
    gemm_qgkv_bf<<<dim3(4, 200, 2), 256, SMEM_GBF>>>(XTH, WQH, qg_b, WKH, kv_b,
        pos, INV, PW, QP, QN, G, KP, KN, V);
    // 4. fused: reductions + dwc5x5 + SE
    k_fused<<<1600, 256>>>(KP, KN, V, KM, KVS, KVO, dwc_w, dwc_b, VD, src, se_w, SE);
    // 5. attention output + vd + gate -> bf16
    k_attn_out<<<512, 256>>>(QP, QN, KM, KVS, KVO, VD, G, OUT2H);
    // 6. proj + residual + LN1 -> S fp32 + SH bf16
    gemm_bf_ln<256,true><<<200, 512, SMEM_GBLN>>>(OUT2H, WPJH, proj_b, XT, ln1_w, ln1_b, S, SH);
    // 7. pin -> YH bf16
    gemm_bf<true><<<dim3(8, 200), 256, SMEM_GBF>>>(SH, WPIH, YH, TOKS, 1024, 256);
    // 8. dw3x3 + glu + se -> Y2H bf16
    k_dw_glu<<<dim3(4, 4, BATCH), 256, SMEM_DG>>>(YH, dw_w, SE, Y2H);
    // 9. pout + residual + LN2 -> TMP
    gemm_bf_ln<512,false><<<200, 512, SMEM_GBLN>>>(Y2H, WPOH, nullptr, S, ln2_w, ln2_b, TMP, nullptr);
    // 10. transpose to NCHW output
    k_tr_out<<<dim3(13, 8, BATCH), dim3(32, 32)>>>(TMP, out);
}